// round 11
// baseline (speedup 1.0000x reference)
#include <cuda_runtime.h>
#include <math.h>

// ---------------- problem constants ----------------
#define BQ     4
#define SEQ    4096
#define DIMX   1024
#define HEADS  16
#define DH     64
#define DI     1024
#define MROWS  (BQ*SEQ)     // 16384
#define QKVN   3072

typedef unsigned long long u64;

// ---------------- scratch (device globals; no allocation) ----------------
__device__ float g_xn [(size_t)MROWS * DIMX];   //  64 MB
__device__ float g_qkv[(size_t)MROWS * QKVN];   // 192 MB
__device__ float g_ao [(size_t)MROWS * DI];     //  64 MB
__device__ float g_sim [64 * 64 * 64];          // raw Gram per (b,h)
__device__ float g_attn[64 * 64 * 64];
__device__ float g_ssq[64 * 64];                // sum q^2 per (bh, d)
__device__ float g_ssk[64 * 64];                // sum k^2 per (bh, e)

// ---------------- streams/events for overlap (created at load, before harness checkpoints) ----
static cudaStream_t g_s2;
static cudaEvent_t  g_evStart, g_evRms01, g_evG1b1, g_evG1b2, g_evSim3, g_evSm, g_evFinal;
namespace {
struct StreamInit {
    StreamInit() {
        cudaStreamCreateWithFlags(&g_s2, cudaStreamNonBlocking);
        cudaEventCreateWithFlags(&g_evStart, cudaEventDisableTiming);
        cudaEventCreateWithFlags(&g_evRms01, cudaEventDisableTiming);
        cudaEventCreateWithFlags(&g_evG1b1,  cudaEventDisableTiming);
        cudaEventCreateWithFlags(&g_evG1b2,  cudaEventDisableTiming);
        cudaEventCreateWithFlags(&g_evSim3,  cudaEventDisableTiming);
        cudaEventCreateWithFlags(&g_evSm,    cudaEventDisableTiming);
        cudaEventCreateWithFlags(&g_evFinal, cudaEventDisableTiming);
    }
} g_si;
}

// ---------------- f32x2 helpers ----------------
__device__ __forceinline__ u64 pk2(float lo, float hi) {
    u64 r;
    asm("mov.b64 %0, {%1, %2};" : "=l"(r)
        : "r"(__float_as_uint(lo)), "r"(__float_as_uint(hi)));
    return r;
}
__device__ __forceinline__ u64 pkdup(float v) {
    u64 r;
    asm("mov.b64 %0, {%1, %1};" : "=l"(r) : "r"(__float_as_uint(v)));
    return r;
}
__device__ __forceinline__ void unpk2(u64 u, float& lo, float& hi) {
    unsigned int a, b;
    asm("mov.b64 {%0, %1}, %2;" : "=r"(a), "=r"(b) : "l"(u));
    lo = __uint_as_float(a);
    hi = __uint_as_float(b);
}
#define FFMA2(c, a, b) asm("fma.rn.f32x2 %0, %1, %2, %0;" : "+l"(c) : "l"(a), "l"(b))

// ---------------- kernel 1: RMSNorm chunk (+ folded accumulator zeroing in rows<1024) ----------
__global__ __launch_bounds__(256) void k_rmsnorm(const float* __restrict__ x,
                                                 const float* __restrict__ gamma,
                                                 int rowoff) {
    int row = rowoff + blockIdx.x;
    int t = threadIdx.x;

    if (row < 1024) {
        int i = row * 256 + t;
        if (i < 64 * 64 * 64) g_sim[i] = 0.0f;
        if (i < 64 * 64) { g_ssq[i] = 0.0f; g_ssk[i] = 0.0f; }
    }

    const float4* xr = (const float4*)(x + (size_t)row * DIMX);
    float4 v = xr[t];
    float ss = v.x * v.x + v.y * v.y + v.z * v.z + v.w * v.w;
    __shared__ float red[8];
    #pragma unroll
    for (int o = 16; o; o >>= 1) ss += __shfl_xor_sync(0xffffffffu, ss, o);
    if ((t & 31) == 0) red[t >> 5] = ss;
    __syncthreads();
    if (t < 8) {
        float s2 = red[t];
        #pragma unroll
        for (int o = 4; o; o >>= 1) s2 += __shfl_xor_sync(0xffu, s2, o);
        if (t == 0) red[0] = s2;
    }
    __syncthreads();
    float norm = sqrtf(red[0]);
    float scale = 32.0f / fmaxf(norm, 1e-12f);
    float4 g = ((const float4*)gamma)[t];
    float4 o;
    o.x = v.x * scale * g.x;
    o.y = v.y * scale * g.y;
    o.z = v.z * scale * g.z;
    o.w = v.w * scale * g.w;
    ((float4*)(g_xn + (size_t)row * DIMX))[t] = o;
}

// ---------------- GEMM body (proven R8/R10 core, + row offset for chunking) ----------------
#define ASTRIDE 132
template <int NDIM>
__device__ __forceinline__ void gemm_body(const float* __restrict__ A,
                                          const float* __restrict__ Bm,
                                          float* __restrict__ C, int rowoff) {
    constexpr int K = 1024;
    __shared__ float As[2][16][ASTRIDE];
    __shared__ float Bs[2][16][128];

    const int tid = threadIdx.x;
    const int tx = tid & 15;
    const int ty = tid >> 4;
    const int row0 = rowoff + blockIdx.y * 128;
    const int col0 = blockIdx.x * 128;

    const int ar = tid >> 2;
    const int ak = (tid & 3) * 4;
    const int bk = tid >> 5;
    const int bn = (tid & 31) * 4;

    const float* Aptr = A + (size_t)(row0 + ar) * K + ak;
    const float* Bptr = Bm + (size_t)bk * NDIM + col0 + bn;

    u64 acc[8][4];
    #pragma unroll
    for (int i = 0; i < 8; i++)
        #pragma unroll
        for (int j = 0; j < 4; j++) acc[i][j] = 0ull;

    float4 a0 = *(const float4*)Aptr;
    float4 a1 = *(const float4*)(Aptr + (size_t)64 * K);
    float4 b0 = *(const float4*)Bptr;
    float4 b1 = *(const float4*)(Bptr + (size_t)8 * NDIM);

    As[0][ak + 0][ar] = a0.x; As[0][ak + 1][ar] = a0.y;
    As[0][ak + 2][ar] = a0.z; As[0][ak + 3][ar] = a0.w;
    As[0][ak + 0][64 + ar] = a1.x; As[0][ak + 1][64 + ar] = a1.y;
    As[0][ak + 2][64 + ar] = a1.z; As[0][ak + 3][64 + ar] = a1.w;
    *(float4*)&Bs[0][bk][bn] = b0;
    *(float4*)&Bs[0][bk + 8][bn] = b1;
    __syncthreads();

    const int NT = K / 16;
    for (int t = 0; t < NT; t++) {
        const int cur = t & 1;
        if (t + 1 < NT) {
            const float* Ap = A + (size_t)(row0 + ar) * K + (t + 1) * 16 + ak;
            a0 = *(const float4*)Ap;
            a1 = *(const float4*)(Ap + (size_t)64 * K);
            const float* Bp = Bm + (size_t)((t + 1) * 16 + bk) * NDIM + col0 + bn;
            b0 = *(const float4*)Bp;
            b1 = *(const float4*)(Bp + (size_t)8 * NDIM);
        }
        #pragma unroll
        for (int k = 0; k < 16; k++) {
            float4 av0 = *(const float4*)&As[cur][k][ty * 4];
            float4 av1 = *(const float4*)&As[cur][k][64 + ty * 4];
            float4 bv0 = *(const float4*)&Bs[cur][k][tx * 4];
            float4 bv1 = *(const float4*)&Bs[cur][k][64 + tx * 4];
            u64 bp0 = pk2(bv0.x, bv0.y), bp1 = pk2(bv0.z, bv0.w);
            u64 bp2 = pk2(bv1.x, bv1.y), bp3 = pk2(bv1.z, bv1.w);
            float a[8] = {av0.x, av0.y, av0.z, av0.w, av1.x, av1.y, av1.z, av1.w};
            #pragma unroll
            for (int i = 0; i < 8; i++) {
                u64 ap = pkdup(a[i]);
                FFMA2(acc[i][0], ap, bp0);
                FFMA2(acc[i][1], ap, bp1);
                FFMA2(acc[i][2], ap, bp2);
                FFMA2(acc[i][3], ap, bp3);
            }
        }
        if (t + 1 < NT) {
            const int nxt = cur ^ 1;
            As[nxt][ak + 0][ar] = a0.x; As[nxt][ak + 1][ar] = a0.y;
            As[nxt][ak + 2][ar] = a0.z; As[nxt][ak + 3][ar] = a0.w;
            As[nxt][ak + 0][64 + ar] = a1.x; As[nxt][ak + 1][64 + ar] = a1.y;
            As[nxt][ak + 2][64 + ar] = a1.z; As[nxt][ak + 3][64 + ar] = a1.w;
            *(float4*)&Bs[nxt][bk][bn] = b0;
            *(float4*)&Bs[nxt][bk + 8][bn] = b1;
            __syncthreads();
        }
    }

    #pragma unroll
    for (int i = 0; i < 8; i++) {
        int r = row0 + ((i < 4) ? (ty * 4 + i) : (64 + ty * 4 + i - 4));
        float x0, x1, x2, x3, x4, x5, x6, x7;
        unpk2(acc[i][0], x0, x1);
        unpk2(acc[i][1], x2, x3);
        unpk2(acc[i][2], x4, x5);
        unpk2(acc[i][3], x6, x7);
        float4 o0 = make_float4(x0, x1, x2, x3);
        float4 o1 = make_float4(x4, x5, x6, x7);
        *(float4*)&C[(size_t)r * NDIM + col0 + tx * 4] = o0;
        *(float4*)&C[(size_t)r * NDIM + col0 + 64 + tx * 4] = o1;
    }
}

__global__ __launch_bounds__(256, 2) void k_gemm_qkv(const float* __restrict__ w, int rowoff) {
    gemm_body<QKVN>(g_xn, w, g_qkv, rowoff);
}
__global__ __launch_bounds__(256, 2) void k_gemm_out(const float* __restrict__ w,
                                                     float* __restrict__ out, int rowoff) {
    gemm_body<DI>(g_ao, w, out, rowoff);
}

// ---------------- kernel 3a: raw Gram chunk (proven R8 core, + bh offset) ----------------
__global__ __launch_bounds__(256) void k_sim(int bhoff) {
    const int bh = bhoff + blockIdx.x;
    const int split = blockIdx.y;     // 0..15, 256 n each
    const int b = bh >> 4, h = bh & 15;
    const int tid = threadIdx.x;
    const int tx = tid & 15, ty = tid >> 4;

    __shared__ float qs[32][64];
    __shared__ float ks[32][64];

    float acc[4][4];
    #pragma unroll
    for (int i = 0; i < 4; i++)
        #pragma unroll
        for (int j = 0; j < 4; j++) acc[i][j] = 0.0f;

    float sq0 = 0, sq1 = 0, sq2 = 0, sq3 = 0;
    float sk0 = 0, sk1 = 0, sk2 = 0, sk3 = 0;

    const size_t basep = ((size_t)b * SEQ) * QKVN + (size_t)h * DH;
    const int nnA = tid >> 4;
    const int dA = (tid & 15) * 4;

    for (int t = 0; t < 8; t++) {
        const int n = split * 256 + t * 32;
        const float* qg = g_qkv + basep + (size_t)n * QKVN;

        float4 q0 = *(const float4*)(qg + (size_t)nnA * QKVN + dA);
        float4 q1 = *(const float4*)(qg + (size_t)(nnA + 16) * QKVN + dA);
        float4 k0 = *(const float4*)(qg + DI + (size_t)nnA * QKVN + dA);
        float4 k1 = *(const float4*)(qg + DI + (size_t)(nnA + 16) * QKVN + dA);

        sq0 += q0.x * q0.x + q1.x * q1.x;
        sq1 += q0.y * q0.y + q1.y * q1.y;
        sq2 += q0.z * q0.z + q1.z * q1.z;
        sq3 += q0.w * q0.w + q1.w * q1.w;
        sk0 += k0.x * k0.x + k1.x * k1.x;
        sk1 += k0.y * k0.y + k1.y * k1.y;
        sk2 += k0.z * k0.z + k1.z * k1.z;
        sk3 += k0.w * k0.w + k1.w * k1.w;

        __syncthreads();
        *(float4*)&qs[nnA][dA] = q0;
        *(float4*)&qs[nnA + 16][dA] = q1;
        *(float4*)&ks[nnA][dA] = k0;
        *(float4*)&ks[nnA + 16][dA] = k1;
        __syncthreads();

        #pragma unroll 8
        for (int nn = 0; nn < 32; nn++) {
            float4 qa = *(const float4*)&qs[nn][ty * 4];
            float4 kb = *(const float4*)&ks[nn][tx * 4];
            float aa[4] = {qa.x, qa.y, qa.z, qa.w};
            float bb[4] = {kb.x, kb.y, kb.z, kb.w};
            #pragma unroll
            for (int i = 0; i < 4; i++)
                #pragma unroll
                for (int j = 0; j < 4; j++)
                    acc[i][j] = fmaf(aa[i], bb[j], acc[i][j]);
        }
    }

    float* simp = g_sim + bh * 4096;
    #pragma unroll
    for (int i = 0; i < 4; i++)
        #pragma unroll
        for (int j = 0; j < 4; j++)
            atomicAdd(&simp[(ty * 4 + i) * 64 + tx * 4 + j], acc[i][j]);

    atomicAdd(&g_ssq[bh * 64 + dA + 0], sq0);
    atomicAdd(&g_ssq[bh * 64 + dA + 1], sq1);
    atomicAdd(&g_ssq[bh * 64 + dA + 2], sq2);
    atomicAdd(&g_ssq[bh * 64 + dA + 3], sq3);
    atomicAdd(&g_ssk[bh * 64 + dA + 0], sk0);
    atomicAdd(&g_ssk[bh * 64 + dA + 1], sk1);
    atomicAdd(&g_ssk[bh * 64 + dA + 2], sk2);
    atomicAdd(&g_ssk[bh * 64 + dA + 3], sk3);
}

// ---------------- kernel 3b: scale + softmax over e ----------------
__global__ __launch_bounds__(256) void k_softmax(const float* __restrict__ temperature) {
    const int bh = blockIdx.x;
    const int tid = threadIdx.x;
    const int d = tid >> 2;
    const int sub = tid & 3;
    const int h = bh & 15;
    const float tscale = 8.0f * expf(temperature[h]);

    __shared__ float rk[64];
    if (tid < 64) rk[tid] = 1.0f / fmaxf(sqrtf(g_ssk[bh * 64 + tid]), 1e-12f);
    __syncthreads();

    const float rq = 1.0f / fmaxf(sqrtf(g_ssq[bh * 64 + d]), 1e-12f);
    const float* srow = g_sim + bh * 4096 + d * 64 + sub * 16;

    float s[16];
    float mx = -1e30f;
    const float sc = tscale * rq;
    #pragma unroll
    for (int j = 0; j < 16; j++) {
        s[j] = srow[j] * sc * rk[sub * 16 + j];
        mx = fmaxf(mx, s[j]);
    }
    mx = fmaxf(mx, __shfl_xor_sync(0xffffffffu, mx, 1));
    mx = fmaxf(mx, __shfl_xor_sync(0xffffffffu, mx, 2));
    float sum = 0.0f;
    #pragma unroll
    for (int j = 0; j < 16; j++) {
        s[j] = expf(s[j] - mx);
        sum += s[j];
    }
    sum += __shfl_xor_sync(0xffffffffu, sum, 1);
    sum += __shfl_xor_sync(0xffffffffu, sum, 2);
    const float inv = 1.0f / sum;
    float* arow = g_attn + bh * 4096 + d * 64 + sub * 16;
    #pragma unroll
    for (int j = 0; j < 16; j += 4) {
        float4 o = make_float4(s[j] * inv, s[j + 1] * inv, s[j + 2] * inv, s[j + 3] * inv);
        *(float4*)&arow[j] = o;
    }
}

// ---------------- kernel 3c: out = attn @ v chunk (proven R8 core, + bh offset) -------------
__global__ __launch_bounds__(256) void k_av(int bhoff) {
    const int bh = bhoff + blockIdx.x;
    const int split = blockIdx.y;  // 0..15
    const int b = bh >> 4, h = bh & 15;
    const int tid = threadIdx.x;
    const int tx = tid & 15, ty = tid >> 4;

    __shared__ float at[64][68];
    __shared__ float vt[64][68];

    const float* ap = g_attn + bh * 4096;
    #pragma unroll
    for (int i = 0; i < 16; i++) {
        int idx = tid + i * 256;
        at[idx & 63][idx >> 6] = ap[idx];
    }

    const size_t vbase = ((size_t)b * SEQ) * QKVN + 2 * DI + (size_t)h * DH;

    for (int t = 0; t < 4; t++) {
        const int n0 = split * 256 + t * 64;
        __syncthreads();
        #pragma unroll
        for (int i = 0; i < 4; i++) {
            int f = tid + i * 256;
            int nn = f >> 4;
            int ec = (f & 15) * 4;
            float4 v4 = *(const float4*)(g_qkv + vbase + (size_t)(n0 + nn) * QKVN + ec);
            vt[ec + 0][nn] = v4.x;
            vt[ec + 1][nn] = v4.y;
            vt[ec + 2][nn] = v4.z;
            vt[ec + 3][nn] = v4.w;
        }
        __syncthreads();

        float acc[4][4];
        #pragma unroll
        for (int j = 0; j < 4; j++)
            #pragma unroll
            for (int i = 0; i < 4; i++) acc[j][i] = 0.0f;

        #pragma unroll 8
        for (int e = 0; e < 64; e++) {
            float4 a4 = *(const float4*)&at[e][tx * 4];
            float4 v4 = *(const float4*)&vt[e][ty * 4];
            float aa[4] = {a4.x, a4.y, a4.z, a4.w};
            float vv[4] = {v4.x, v4.y, v4.z, v4.w};
            #pragma unroll
            for (int j = 0; j < 4; j++)
                #pragma unroll
                for (int i = 0; i < 4; i++)
                    acc[j][i] = fmaf(vv[j], aa[i], acc[j][i]);
        }

        #pragma unroll
        for (int j = 0; j < 4; j++) {
            int n = n0 + ty * 4 + j;
            float4 o = make_float4(acc[j][0], acc[j][1], acc[j][2], acc[j][3]);
            *(float4*)&g_ao[(size_t)(b * SEQ + n) * DI + h * DH + tx * 4] = o;
        }
    }
}

// ---------------- launch: two-stream pipelined schedule ----------------
extern "C" void kernel_launch(void* const* d_in, const int* in_sizes, int n_in,
                              void* d_out, int out_size) {
    const float* x = (const float*)d_in[0];
    const float* gamma = (const float*)d_in[1];
    const float* w_qkv = (const float*)d_in[2];
    const float* temperature = (const float*)d_in[3];
    const float* w_out = (const float*)d_in[4];
    float* out = (float*)d_out;

    cudaStream_t s0 = 0;

    // fork s2 from the origin stream
    cudaEventRecord(g_evStart, s0);
    cudaStreamWaitEvent(g_s2, g_evStart, 0);

    // rmsnorm halves (concurrent); b01 chunk also zeroes the small accumulators
    k_rmsnorm<<<8192, 256, 0, s0>>>(x, gamma, 0);
    cudaEventRecord(g_evRms01, s0);
    k_rmsnorm<<<8192, 256, 0, g_s2>>>(x, gamma, 8192);

    // GEMM1 chunks: b0 on s0; b1..b3 on s2 (s2 must see rms01 for b1 rows)
    k_gemm_qkv<<<dim3(QKVN / 128, 32), 256, 0, s0>>>(w_qkv, 0);
    cudaStreamWaitEvent(g_s2, g_evRms01, 0);
    k_gemm_qkv<<<dim3(QKVN / 128, 32), 256, 0, g_s2>>>(w_qkv, 4096);
    cudaEventRecord(g_evG1b1, g_s2);
    k_gemm_qkv<<<dim3(QKVN / 128, 32), 256, 0, g_s2>>>(w_qkv, 8192);
    cudaEventRecord(g_evG1b2, g_s2);
    k_gemm_qkv<<<dim3(QKVN / 128, 32), 256, 0, g_s2>>>(w_qkv, 12288);

    // sims: b0..b2 on s0 (progressively unblocked -> fill G1 tails), b3 on s2
    k_sim<<<dim3(16, 16), 256, 0, s0>>>(0);
    cudaStreamWaitEvent(s0, g_evG1b1, 0);
    k_sim<<<dim3(16, 16), 256, 0, s0>>>(16);
    cudaStreamWaitEvent(s0, g_evG1b2, 0);
    k_sim<<<dim3(16, 16), 256, 0, s0>>>(32);
    k_sim<<<dim3(16, 16), 256, 0, g_s2>>>(48);
    cudaEventRecord(g_evSim3, g_s2);

    // softmax (needs all sims)
    cudaStreamWaitEvent(s0, g_evSim3, 0);
    k_softmax<<<64, 256, 0, s0>>>(temperature);
    cudaEventRecord(g_evSm, s0);

    // av + GEMM2 pipelined: b0 on s0, b1..b3 on s2
    k_av<<<dim3(16, 16), 256, 0, s0>>>(0);
    k_gemm_out<<<dim3(DI / 128, 32), 256, 0, s0>>>(w_out, out, 0);
    cudaStreamWaitEvent(g_s2, g_evSm, 0);
    k_av<<<dim3(16, 16), 256, 0, g_s2>>>(16);
    k_gemm_out<<<dim3(DI / 128, 32), 256, 0, g_s2>>>(w_out, out, 4096);
    k_av<<<dim3(16, 16), 256, 0, g_s2>>>(32);
    k_gemm_out<<<dim3(DI / 128, 32), 256, 0, g_s2>>>(w_out, out, 8192);
    k_av<<<dim3(16, 16), 256, 0, g_s2>>>(48);
    k_gemm_out<<<dim3(DI / 128, 32), 256, 0, g_s2>>>(w_out, out, 12288);

    // join s2 back into origin
    cudaEventRecord(g_evFinal, g_s2);
    cudaStreamWaitEvent(s0, g_evFinal, 0);
}

// round 12
// speedup vs baseline: 1.1713x; 1.1713x over previous
#include <cuda_runtime.h>
#include <math.h>

// ---------------- problem constants ----------------
#define BQ     4
#define SEQ    4096
#define DIMX   1024
#define HEADS  16
#define DH     64
#define DI     1024
#define MROWS  (BQ*SEQ)     // 16384
#define QKVN   3072

typedef unsigned long long u64;

// ---------------- scratch (device globals; no allocation) ----------------
__device__ float g_xn [(size_t)MROWS * DIMX];   //  64 MB
__device__ float g_qkv[(size_t)MROWS * QKVN];   // 192 MB
__device__ float g_M  [(size_t)BQ * DI * DI];   //  16 MB: per-batch  M_b = attn_b^T-contracted w_out
__device__ float g_sim [64 * 64 * 64];          // raw Gram per (b,h)
__device__ float g_attn[64 * 64 * 64];
__device__ float g_ssq[64 * 64];                // sum q^2 per (bh, d)
__device__ float g_ssk[64 * 64];                // sum k^2 per (bh, e)

// ---------------- f32x2 helpers ----------------
__device__ __forceinline__ u64 pk2(float lo, float hi) {
    u64 r;
    asm("mov.b64 %0, {%1, %2};" : "=l"(r)
        : "r"(__float_as_uint(lo)), "r"(__float_as_uint(hi)));
    return r;
}
__device__ __forceinline__ u64 pkdup(float v) {
    u64 r;
    asm("mov.b64 %0, {%1, %1};" : "=l"(r) : "r"(__float_as_uint(v)));
    return r;
}
__device__ __forceinline__ void unpk2(u64 u, float& lo, float& hi) {
    unsigned int a, b;
    asm("mov.b64 {%0, %1}, %2;" : "=r"(a), "=r"(b) : "l"(u));
    lo = __uint_as_float(a);
    hi = __uint_as_float(b);
}
#define FFMA2(c, a, b) asm("fma.rn.f32x2 %0, %1, %2, %0;" : "+l"(c) : "l"(a), "l"(b))

// ---------------- kernel 1: RMSNorm (+ folded accumulator zeroing) ----------------
__global__ __launch_bounds__(256) void k_rmsnorm(const float* __restrict__ x,
                                                 const float* __restrict__ gamma) {
    int row = blockIdx.x;
    int t = threadIdx.x;

    if (row < 1024) {
        int i = row * 256 + t;
        if (i < 64 * 64 * 64) g_sim[i] = 0.0f;
        if (i < 64 * 64) { g_ssq[i] = 0.0f; g_ssk[i] = 0.0f; }
    }

    const float4* xr = (const float4*)(x + (size_t)row * DIMX);
    float4 v = xr[t];
    float ss = v.x * v.x + v.y * v.y + v.z * v.z + v.w * v.w;
    __shared__ float red[8];
    #pragma unroll
    for (int o = 16; o; o >>= 1) ss += __shfl_xor_sync(0xffffffffu, ss, o);
    if ((t & 31) == 0) red[t >> 5] = ss;
    __syncthreads();
    if (t < 8) {
        float s2 = red[t];
        #pragma unroll
        for (int o = 4; o; o >>= 1) s2 += __shfl_xor_sync(0xffu, s2, o);
        if (t == 0) red[0] = s2;
    }
    __syncthreads();
    float norm = sqrtf(red[0]);
    float scale = 32.0f / fmaxf(norm, 1e-12f);
    float4 g = ((const float4*)gamma)[t];
    float4 o;
    o.x = v.x * scale * g.x;
    o.y = v.y * scale * g.y;
    o.z = v.z * scale * g.z;
    o.w = v.w * scale * g.w;
    ((float4*)(g_xn + (size_t)row * DIMX))[t] = o;
}

// ---------------- GEMM body (proven R8/R10 core; AST = A row stride, K extent 1024) ---------
#define ASTRIDE 132
template <int NDIM, int AST>
__device__ __forceinline__ void gemm_body(const float* __restrict__ A,
                                          const float* __restrict__ Bm,
                                          float* __restrict__ C) {
    constexpr int K = 1024;
    __shared__ float As[2][16][ASTRIDE];
    __shared__ float Bs[2][16][128];

    const int tid = threadIdx.x;
    const int tx = tid & 15;
    const int ty = tid >> 4;
    const int row0 = blockIdx.y * 128;
    const int col0 = blockIdx.x * 128;

    const int ar = tid >> 2;          // 0..63 (second load covers 64..127)
    const int ak = (tid & 3) * 4;     // 0,4,8,12
    const int bk = tid >> 5;          // 0..7  (second load covers 8..15)
    const int bn = (tid & 31) * 4;    // 0..124

    const float* Aptr = A + (size_t)(row0 + ar) * AST + ak;
    const float* Bptr = Bm + (size_t)bk * NDIM + col0 + bn;

    u64 acc[8][4];
    #pragma unroll
    for (int i = 0; i < 8; i++)
        #pragma unroll
        for (int j = 0; j < 4; j++) acc[i][j] = 0ull;

    float4 a0 = *(const float4*)Aptr;
    float4 a1 = *(const float4*)(Aptr + (size_t)64 * AST);
    float4 b0 = *(const float4*)Bptr;
    float4 b1 = *(const float4*)(Bptr + (size_t)8 * NDIM);

    As[0][ak + 0][ar] = a0.x; As[0][ak + 1][ar] = a0.y;
    As[0][ak + 2][ar] = a0.z; As[0][ak + 3][ar] = a0.w;
    As[0][ak + 0][64 + ar] = a1.x; As[0][ak + 1][64 + ar] = a1.y;
    As[0][ak + 2][64 + ar] = a1.z; As[0][ak + 3][64 + ar] = a1.w;
    *(float4*)&Bs[0][bk][bn] = b0;
    *(float4*)&Bs[0][bk + 8][bn] = b1;
    __syncthreads();

    const int NT = K / 16;
    for (int t = 0; t < NT; t++) {
        const int cur = t & 1;
        if (t + 1 < NT) {
            const float* Ap = A + (size_t)(row0 + ar) * AST + (t + 1) * 16 + ak;
            a0 = *(const float4*)Ap;
            a1 = *(const float4*)(Ap + (size_t)64 * AST);
            const float* Bp = Bm + (size_t)((t + 1) * 16 + bk) * NDIM + col0 + bn;
            b0 = *(const float4*)Bp;
            b1 = *(const float4*)(Bp + (size_t)8 * NDIM);
        }
        #pragma unroll
        for (int k = 0; k < 16; k++) {
            float4 av0 = *(const float4*)&As[cur][k][ty * 4];
            float4 av1 = *(const float4*)&As[cur][k][64 + ty * 4];
            float4 bv0 = *(const float4*)&Bs[cur][k][tx * 4];
            float4 bv1 = *(const float4*)&Bs[cur][k][64 + tx * 4];
            u64 bp0 = pk2(bv0.x, bv0.y), bp1 = pk2(bv0.z, bv0.w);
            u64 bp2 = pk2(bv1.x, bv1.y), bp3 = pk2(bv1.z, bv1.w);
            float a[8] = {av0.x, av0.y, av0.z, av0.w, av1.x, av1.y, av1.z, av1.w};
            #pragma unroll
            for (int i = 0; i < 8; i++) {
                u64 ap = pkdup(a[i]);
                FFMA2(acc[i][0], ap, bp0);
                FFMA2(acc[i][1], ap, bp1);
                FFMA2(acc[i][2], ap, bp2);
                FFMA2(acc[i][3], ap, bp3);
            }
        }
        if (t + 1 < NT) {
            // single-barrier double buffering
            const int nxt = cur ^ 1;
            As[nxt][ak + 0][ar] = a0.x; As[nxt][ak + 1][ar] = a0.y;
            As[nxt][ak + 2][ar] = a0.z; As[nxt][ak + 3][ar] = a0.w;
            As[nxt][ak + 0][64 + ar] = a1.x; As[nxt][ak + 1][64 + ar] = a1.y;
            As[nxt][ak + 2][64 + ar] = a1.z; As[nxt][ak + 3][64 + ar] = a1.w;
            *(float4*)&Bs[nxt][bk][bn] = b0;
            *(float4*)&Bs[nxt][bk + 8][bn] = b1;
            __syncthreads();
        }
    }

    #pragma unroll
    for (int i = 0; i < 8; i++) {
        int r = row0 + ((i < 4) ? (ty * 4 + i) : (64 + ty * 4 + i - 4));
        float x0, x1, x2, x3, x4, x5, x6, x7;
        unpk2(acc[i][0], x0, x1);
        unpk2(acc[i][1], x2, x3);
        unpk2(acc[i][2], x4, x5);
        unpk2(acc[i][3], x6, x7);
        float4 o0 = make_float4(x0, x1, x2, x3);
        float4 o1 = make_float4(x4, x5, x6, x7);
        *(float4*)&C[(size_t)r * NDIM + col0 + tx * 4] = o0;
        *(float4*)&C[(size_t)r * NDIM + col0 + 64 + tx * 4] = o1;
    }
}

__global__ __launch_bounds__(256, 2) void k_gemm_qkv(const float* __restrict__ w) {
    gemm_body<QKVN, 1024>(g_xn, w, g_qkv);
}
// GEMM2: out[row, j] = sum_k v[row, k] * M_b[k, j], v read in place from g_qkv (stride 3072),
// B = per-batch M (batch = row0 / 4096; each 128-row block lies in one batch).
__global__ __launch_bounds__(256, 2) void k_gemm_out(float* __restrict__ out) {
    const float* Mb = g_M + (size_t)(blockIdx.y >> 5) * DI * DI;
    gemm_body<DI, QKVN>(g_qkv + 2 * DI, Mb, out);
}

// ---------------- kernel 3a: raw Gram sim[d][e] += q.k over n-split; also sumsq ----------------
__global__ __launch_bounds__(256) void k_sim() {
    const int bh = blockIdx.x;        // b*16 + h
    const int split = blockIdx.y;     // 0..15, 256 n each
    const int b = bh >> 4, h = bh & 15;
    const int tid = threadIdx.x;
    const int tx = tid & 15, ty = tid >> 4;

    __shared__ float qs[32][64];
    __shared__ float ks[32][64];

    float acc[4][4];
    #pragma unroll
    for (int i = 0; i < 4; i++)
        #pragma unroll
        for (int j = 0; j < 4; j++) acc[i][j] = 0.0f;

    float sq0 = 0, sq1 = 0, sq2 = 0, sq3 = 0;
    float sk0 = 0, sk1 = 0, sk2 = 0, sk3 = 0;

    const size_t basep = ((size_t)b * SEQ) * QKVN + (size_t)h * DH;
    const int nnA = tid >> 4;          // 0..15
    const int dA = (tid & 15) * 4;     // 0..60

    for (int t = 0; t < 8; t++) {
        const int n = split * 256 + t * 32;
        const float* qg = g_qkv + basep + (size_t)n * QKVN;

        float4 q0 = *(const float4*)(qg + (size_t)nnA * QKVN + dA);
        float4 q1 = *(const float4*)(qg + (size_t)(nnA + 16) * QKVN + dA);
        float4 k0 = *(const float4*)(qg + DI + (size_t)nnA * QKVN + dA);
        float4 k1 = *(const float4*)(qg + DI + (size_t)(nnA + 16) * QKVN + dA);

        sq0 += q0.x * q0.x + q1.x * q1.x;
        sq1 += q0.y * q0.y + q1.y * q1.y;
        sq2 += q0.z * q0.z + q1.z * q1.z;
        sq3 += q0.w * q0.w + q1.w * q1.w;
        sk0 += k0.x * k0.x + k1.x * k1.x;
        sk1 += k0.y * k0.y + k1.y * k1.y;
        sk2 += k0.z * k0.z + k1.z * k1.z;
        sk3 += k0.w * k0.w + k1.w * k1.w;

        __syncthreads();
        *(float4*)&qs[nnA][dA] = q0;
        *(float4*)&qs[nnA + 16][dA] = q1;
        *(float4*)&ks[nnA][dA] = k0;
        *(float4*)&ks[nnA + 16][dA] = k1;
        __syncthreads();

        #pragma unroll 8
        for (int nn = 0; nn < 32; nn++) {
            float4 qa = *(const float4*)&qs[nn][ty * 4];
            float4 kb = *(const float4*)&ks[nn][tx * 4];
            float aa[4] = {qa.x, qa.y, qa.z, qa.w};
            float bb[4] = {kb.x, kb.y, kb.z, kb.w};
            #pragma unroll
            for (int i = 0; i < 4; i++)
                #pragma unroll
                for (int j = 0; j < 4; j++)
                    acc[i][j] = fmaf(aa[i], bb[j], acc[i][j]);
        }
    }

    float* simp = g_sim + bh * 4096;
    #pragma unroll
    for (int i = 0; i < 4; i++)
        #pragma unroll
        for (int j = 0; j < 4; j++)
            atomicAdd(&simp[(ty * 4 + i) * 64 + tx * 4 + j], acc[i][j]);

    atomicAdd(&g_ssq[bh * 64 + dA + 0], sq0);
    atomicAdd(&g_ssq[bh * 64 + dA + 1], sq1);
    atomicAdd(&g_ssq[bh * 64 + dA + 2], sq2);
    atomicAdd(&g_ssq[bh * 64 + dA + 3], sq3);
    atomicAdd(&g_ssk[bh * 64 + dA + 0], sk0);
    atomicAdd(&g_ssk[bh * 64 + dA + 1], sk1);
    atomicAdd(&g_ssk[bh * 64 + dA + 2], sk2);
    atomicAdd(&g_ssk[bh * 64 + dA + 3], sk3);
}

// ---------------- kernel 3b: scale + softmax over e (256 threads: 64 d x 4 e-groups) --------
__global__ __launch_bounds__(256) void k_softmax(const float* __restrict__ temperature) {
    const int bh = blockIdx.x;
    const int tid = threadIdx.x;
    const int d = tid >> 2;          // 0..63
    const int sub = tid & 3;         // e-group: 16 e's each
    const int h = bh & 15;
    const float tscale = 8.0f * expf(temperature[h]);

    __shared__ float rk[64];
    if (tid < 64) rk[tid] = 1.0f / fmaxf(sqrtf(g_ssk[bh * 64 + tid]), 1e-12f);
    __syncthreads();

    const float rq = 1.0f / fmaxf(sqrtf(g_ssq[bh * 64 + d]), 1e-12f);
    const float* srow = g_sim + bh * 4096 + d * 64 + sub * 16;

    float s[16];
    float mx = -1e30f;
    const float sc = tscale * rq;
    #pragma unroll
    for (int j = 0; j < 16; j++) {
        s[j] = srow[j] * sc * rk[sub * 16 + j];
        mx = fmaxf(mx, s[j]);
    }
    mx = fmaxf(mx, __shfl_xor_sync(0xffffffffu, mx, 1));
    mx = fmaxf(mx, __shfl_xor_sync(0xffffffffu, mx, 2));
    float sum = 0.0f;
    #pragma unroll
    for (int j = 0; j < 16; j++) {
        s[j] = expf(s[j] - mx);
        sum += s[j];
    }
    sum += __shfl_xor_sync(0xffffffffu, sum, 1);
    sum += __shfl_xor_sync(0xffffffffu, sum, 2);
    const float inv = 1.0f / sum;
    float* arow = g_attn + bh * 4096 + d * 64 + sub * 16;
    #pragma unroll
    for (int j = 0; j < 16; j += 4) {
        float4 o = make_float4(s[j] * inv, s[j + 1] * inv, s[j + 2] * inv, s[j + 3] * inv);
        *(float4*)&arow[j] = o;
    }
}

// ---------------- kernel 3c: M_b[(h,e), j] = sum_d attn[b,h,d,e] * w_out[(h,d), j] ----------
// grid (bh=64, jtile=8), 256 threads, 64x128 output tile, K=64.
__global__ __launch_bounds__(256) void k_M(const float* __restrict__ W) {
    const int bh = blockIdx.x;
    const int j0 = blockIdx.y * 128;
    const int b = bh >> 4, h = bh & 15;
    const int tid = threadIdx.x;
    const int tx = tid & 15, ty = tid >> 4;

    __shared__ float am[64][64];    // am[d][e] = attn[bh][d*64+e] (natural layout)
    __shared__ float ws[64][132];   // ws[d][jj] = w_out[(h*64+d)][j0+jj]

    const float4* ap4 = (const float4*)(g_attn + bh * 4096);
    #pragma unroll
    for (int i = 0; i < 4; i++)
        ((float4*)am)[tid + i * 256] = ap4[tid + i * 256];
    #pragma unroll
    for (int i = 0; i < 8; i++) {
        int idx = tid + i * 256;
        int d = idx >> 5, jj = (idx & 31) * 4;
        *(float4*)&ws[d][jj] = *(const float4*)&W[(size_t)(h * 64 + d) * DI + j0 + jj];
    }
    __syncthreads();

    float acc[4][8];
    #pragma unroll
    for (int i = 0; i < 4; i++)
        #pragma unroll
        for (int j = 0; j < 8; j++) acc[i][j] = 0.0f;

    #pragma unroll 8
    for (int d = 0; d < 64; d++) {
        float4 a4 = *(const float4*)&am[d][ty * 4];            // e = ty*4..+3
        float4 b0 = *(const float4*)&ws[d][tx * 8];
        float4 b1 = *(const float4*)&ws[d][tx * 8 + 4];
        float aa[4] = {a4.x, a4.y, a4.z, a4.w};
        float bb[8] = {b0.x, b0.y, b0.z, b0.w, b1.x, b1.y, b1.z, b1.w};
        #pragma unroll
        for (int i = 0; i < 4; i++)
            #pragma unroll
            for (int j = 0; j < 8; j++)
                acc[i][j] = fmaf(aa[i], bb[j], acc[i][j]);
    }

    #pragma unroll
    for (int i = 0; i < 4; i++) {
        int he = h * 64 + ty * 4 + i;
        float* mrow = g_M + ((size_t)b * DI + he) * DI + j0 + tx * 8;
        *(float4*)mrow       = make_float4(acc[i][0], acc[i][1], acc[i][2], acc[i][3]);
        *(float4*)(mrow + 4) = make_float4(acc[i][4], acc[i][5], acc[i][6], acc[i][7]);
    }
}

// ---------------- launch ----------------
extern "C" void kernel_launch(void* const* d_in, const int* in_sizes, int n_in,
                              void* d_out, int out_size) {
    const float* x = (const float*)d_in[0];
    const float* gamma = (const float*)d_in[1];
    const float* w_qkv = (const float*)d_in[2];
    const float* temperature = (const float*)d_in[3];
    const float* w_out = (const float*)d_in[4];
    float* out = (float*)d_out;

    k_rmsnorm<<<MROWS, 256>>>(x, gamma);
    k_gemm_qkv<<<dim3(QKVN / 128, MROWS / 128), 256>>>(w_qkv);
    k_sim<<<dim3(64, 16), 256>>>();
    k_softmax<<<64, 256>>>(temperature);
    k_M<<<dim3(64, 8), 256>>>(w_out);
    k_gemm_out<<<dim3(DI / 128, MROWS / 128), 256>>>(out);
}

// round 13
// speedup vs baseline: 1.1802x; 1.0075x over previous
#include <cuda_runtime.h>
#include <math.h>

// ---------------- problem constants ----------------
#define BQ     4
#define SEQ    4096
#define DIMX   1024
#define HEADS  16
#define DH     64
#define DI     1024
#define MROWS  (BQ*SEQ)     // 16384
#define QKVN   3072

typedef unsigned long long u64;

// ---------------- scratch (device globals; no allocation) ----------------
__device__ float g_qkv[(size_t)MROWS * QKVN];   // 192 MB
__device__ float g_wq [(size_t)DIMX * QKVN];    //  12 MB: gamma-folded w_qkv
__device__ float g_rs [MROWS];                  // per-row rmsnorm scale
__device__ float g_M  [(size_t)BQ * DI * DI];   //  16 MB: per-batch M_b
__device__ float g_sim [64 * 64 * 64];          // raw Gram per (b,h)
__device__ float g_attn[64 * 64 * 64];
__device__ float g_ssq[64 * 64];                // sum q^2 per (bh, d)
__device__ float g_ssk[64 * 64];                // sum k^2 per (bh, e)

// ---------------- f32x2 helpers ----------------
__device__ __forceinline__ u64 pk2(float lo, float hi) {
    u64 r;
    asm("mov.b64 %0, {%1, %2};" : "=l"(r)
        : "r"(__float_as_uint(lo)), "r"(__float_as_uint(hi)));
    return r;
}
__device__ __forceinline__ u64 pkdup(float v) {
    u64 r;
    asm("mov.b64 %0, {%1, %1};" : "=l"(r) : "r"(__float_as_uint(v)));
    return r;
}
__device__ __forceinline__ void unpk2(u64 u, float& lo, float& hi) {
    unsigned int a, b;
    asm("mov.b64 {%0, %1}, %2;" : "=r"(a), "=r"(b) : "l"(u));
    lo = __uint_as_float(a);
    hi = __uint_as_float(b);
}
#define FFMA2(c, a, b) asm("fma.rn.f32x2 %0, %1, %2, %0;" : "+l"(c) : "l"(a), "l"(b))

// ---------------- kernel 0a: fold gamma into w_qkv rows ----------------
__global__ __launch_bounds__(256) void k_wfold(const float* __restrict__ w,
                                               const float* __restrict__ gamma) {
    int idx = blockIdx.x * 256 + threadIdx.x;          // float4 index
    int row = idx / (QKVN / 4);
    float g = gamma[row];
    float4 v = ((const float4*)w)[idx];
    v.x *= g; v.y *= g; v.z *= g; v.w *= g;
    ((float4*)g_wq)[idx] = v;
}

// ---------------- kernel 0b: row scales (+ folded accumulator zeroing) ----------------
__global__ __launch_bounds__(256) void k_rscale(const float* __restrict__ x) {
    int row = blockIdx.x;
    int t = threadIdx.x;

    if (row < 1024) {
        int i = row * 256 + t;
        if (i < 64 * 64 * 64) g_sim[i] = 0.0f;
        if (i < 64 * 64) { g_ssq[i] = 0.0f; g_ssk[i] = 0.0f; }
    }

    float4 v = ((const float4*)(x + (size_t)row * DIMX))[t];
    float ss = v.x * v.x + v.y * v.y + v.z * v.z + v.w * v.w;
    __shared__ float red[8];
    #pragma unroll
    for (int o = 16; o; o >>= 1) ss += __shfl_xor_sync(0xffffffffu, ss, o);
    if ((t & 31) == 0) red[t >> 5] = ss;
    __syncthreads();
    if (t < 8) {
        float s2 = red[t];
        #pragma unroll
        for (int o = 4; o; o >>= 1) s2 += __shfl_xor_sync(0xffu, s2, o);
        if (t == 0) g_rs[row] = 32.0f / fmaxf(sqrtf(s2), 1e-12f);
    }
}

// ---------------- GEMM body (proven core; AST = A row stride; optional row-scale epilogue) ----
#define ASTRIDE 132
template <int NDIM, int AST, bool RSCALE>
__device__ __forceinline__ void gemm_body(const float* __restrict__ A,
                                          const float* __restrict__ Bm,
                                          float* __restrict__ C,
                                          const float* __restrict__ rs) {
    constexpr int K = 1024;
    __shared__ float As[2][16][ASTRIDE];
    __shared__ float Bs[2][16][128];

    const int tid = threadIdx.x;
    const int tx = tid & 15;
    const int ty = tid >> 4;
    const int row0 = blockIdx.y * 128;
    const int col0 = blockIdx.x * 128;

    const int ar = tid >> 2;          // 0..63 (second load covers 64..127)
    const int ak = (tid & 3) * 4;     // 0,4,8,12
    const int bk = tid >> 5;          // 0..7  (second load covers 8..15)
    const int bn = (tid & 31) * 4;    // 0..124

    const float* Aptr = A + (size_t)(row0 + ar) * AST + ak;
    const float* Bptr = Bm + (size_t)bk * NDIM + col0 + bn;

    u64 acc[8][4];
    #pragma unroll
    for (int i = 0; i < 8; i++)
        #pragma unroll
        for (int j = 0; j < 4; j++) acc[i][j] = 0ull;

    float4 a0 = *(const float4*)Aptr;
    float4 a1 = *(const float4*)(Aptr + (size_t)64 * AST);
    float4 b0 = *(const float4*)Bptr;
    float4 b1 = *(const float4*)(Bptr + (size_t)8 * NDIM);

    As[0][ak + 0][ar] = a0.x; As[0][ak + 1][ar] = a0.y;
    As[0][ak + 2][ar] = a0.z; As[0][ak + 3][ar] = a0.w;
    As[0][ak + 0][64 + ar] = a1.x; As[0][ak + 1][64 + ar] = a1.y;
    As[0][ak + 2][64 + ar] = a1.z; As[0][ak + 3][64 + ar] = a1.w;
    *(float4*)&Bs[0][bk][bn] = b0;
    *(float4*)&Bs[0][bk + 8][bn] = b1;
    __syncthreads();

    const int NT = K / 16;
    for (int t = 0; t < NT; t++) {
        const int cur = t & 1;
        if (t + 1 < NT) {
            const float* Ap = A + (size_t)(row0 + ar) * AST + (t + 1) * 16 + ak;
            a0 = *(const float4*)Ap;
            a1 = *(const float4*)(Ap + (size_t)64 * AST);
            const float* Bp = Bm + (size_t)((t + 1) * 16 + bk) * NDIM + col0 + bn;
            b0 = *(const float4*)Bp;
            b1 = *(const float4*)(Bp + (size_t)8 * NDIM);
        }
        #pragma unroll
        for (int k = 0; k < 16; k++) {
            float4 av0 = *(const float4*)&As[cur][k][ty * 4];
            float4 av1 = *(const float4*)&As[cur][k][64 + ty * 4];
            float4 bv0 = *(const float4*)&Bs[cur][k][tx * 4];
            float4 bv1 = *(const float4*)&Bs[cur][k][64 + tx * 4];
            u64 bp0 = pk2(bv0.x, bv0.y), bp1 = pk2(bv0.z, bv0.w);
            u64 bp2 = pk2(bv1.x, bv1.y), bp3 = pk2(bv1.z, bv1.w);
            float a[8] = {av0.x, av0.y, av0.z, av0.w, av1.x, av1.y, av1.z, av1.w};
            #pragma unroll
            for (int i = 0; i < 8; i++) {
                u64 ap = pkdup(a[i]);
                FFMA2(acc[i][0], ap, bp0);
                FFMA2(acc[i][1], ap, bp1);
                FFMA2(acc[i][2], ap, bp2);
                FFMA2(acc[i][3], ap, bp3);
            }
        }
        if (t + 1 < NT) {
            // single-barrier double buffering
            const int nxt = cur ^ 1;
            As[nxt][ak + 0][ar] = a0.x; As[nxt][ak + 1][ar] = a0.y;
            As[nxt][ak + 2][ar] = a0.z; As[nxt][ak + 3][ar] = a0.w;
            As[nxt][ak + 0][64 + ar] = a1.x; As[nxt][ak + 1][64 + ar] = a1.y;
            As[nxt][ak + 2][64 + ar] = a1.z; As[nxt][ak + 3][64 + ar] = a1.w;
            *(float4*)&Bs[nxt][bk][bn] = b0;
            *(float4*)&Bs[nxt][bk + 8][bn] = b1;
            __syncthreads();
        }
    }

    #pragma unroll
    for (int i = 0; i < 8; i++) {
        int r = row0 + ((i < 4) ? (ty * 4 + i) : (64 + ty * 4 + i - 4));
        float x0, x1, x2, x3, x4, x5, x6, x7;
        unpk2(acc[i][0], x0, x1);
        unpk2(acc[i][1], x2, x3);
        unpk2(acc[i][2], x4, x5);
        unpk2(acc[i][3], x6, x7);
        if (RSCALE) {
            float s = rs[r];
            x0 *= s; x1 *= s; x2 *= s; x3 *= s;
            x4 *= s; x5 *= s; x6 *= s; x7 *= s;
        }
        float4 o0 = make_float4(x0, x1, x2, x3);
        float4 o1 = make_float4(x4, x5, x6, x7);
        *(float4*)&C[(size_t)r * NDIM + col0 + tx * 4] = o0;
        *(float4*)&C[(size_t)r * NDIM + col0 + 64 + tx * 4] = o1;
    }
}

__global__ __launch_bounds__(256, 2) void k_gemm_qkv(const float* __restrict__ x) {
    gemm_body<QKVN, 1024, true>(x, g_wq, g_qkv, g_rs);
}
// GEMM2: out = v (in place in g_qkv, stride 3072) @ per-batch M
__global__ __launch_bounds__(256, 2) void k_gemm_out(float* __restrict__ out) {
    const float* Mb = g_M + (size_t)(blockIdx.y >> 5) * DI * DI;
    gemm_body<DI, QKVN, false>(g_qkv + 2 * DI, Mb, out, nullptr);
}

// ---------------- kernel 3a: raw Gram sim += q.k over n-split; FFMA2-packed (proven in R9) ----
__global__ __launch_bounds__(256) void k_sim() {
    const int bh = blockIdx.x;        // b*16 + h
    const int split = blockIdx.y;     // 0..15, 256 n each
    const int b = bh >> 4, h = bh & 15;
    const int tid = threadIdx.x;
    const int tx = tid & 15, ty = tid >> 4;

    __shared__ float qs[32][64];
    __shared__ float ks[32][64];

    u64 acc2[4][2];
    #pragma unroll
    for (int i = 0; i < 4; i++) { acc2[i][0] = 0ull; acc2[i][1] = 0ull; }

    float sq0 = 0, sq1 = 0, sq2 = 0, sq3 = 0;
    float sk0 = 0, sk1 = 0, sk2 = 0, sk3 = 0;

    const size_t basep = ((size_t)b * SEQ) * QKVN + (size_t)h * DH;
    const int nnA = tid >> 4;          // 0..15
    const int dA = (tid & 15) * 4;     // 0..60

    for (int t = 0; t < 8; t++) {
        const int n = split * 256 + t * 32;
        const float* qg = g_qkv + basep + (size_t)n * QKVN;

        float4 q0 = *(const float4*)(qg + (size_t)nnA * QKVN + dA);
        float4 q1 = *(const float4*)(qg + (size_t)(nnA + 16) * QKVN + dA);
        float4 k0 = *(const float4*)(qg + DI + (size_t)nnA * QKVN + dA);
        float4 k1 = *(const float4*)(qg + DI + (size_t)(nnA + 16) * QKVN + dA);

        sq0 += q0.x * q0.x + q1.x * q1.x;
        sq1 += q0.y * q0.y + q1.y * q1.y;
        sq2 += q0.z * q0.z + q1.z * q1.z;
        sq3 += q0.w * q0.w + q1.w * q1.w;
        sk0 += k0.x * k0.x + k1.x * k1.x;
        sk1 += k0.y * k0.y + k1.y * k1.y;
        sk2 += k0.z * k0.z + k1.z * k1.z;
        sk3 += k0.w * k0.w + k1.w * k1.w;

        __syncthreads();
        *(float4*)&qs[nnA][dA] = q0;
        *(float4*)&qs[nnA + 16][dA] = q1;
        *(float4*)&ks[nnA][dA] = k0;
        *(float4*)&ks[nnA + 16][dA] = k1;
        __syncthreads();

        #pragma unroll 8
        for (int nn = 0; nn < 32; nn++) {
            float4 qa = *(const float4*)&qs[nn][ty * 4];
            float4 kb = *(const float4*)&ks[nn][tx * 4];
            u64 b01 = pk2(kb.x, kb.y), b23 = pk2(kb.z, kb.w);
            float aa[4] = {qa.x, qa.y, qa.z, qa.w};
            #pragma unroll
            for (int i = 0; i < 4; i++) {
                u64 ad = pkdup(aa[i]);
                FFMA2(acc2[i][0], ad, b01);
                FFMA2(acc2[i][1], ad, b23);
            }
        }
    }

    float* simp = g_sim + bh * 4096;
    #pragma unroll
    for (int i = 0; i < 4; i++) {
        float c0, c1, c2, c3;
        unpk2(acc2[i][0], c0, c1);
        unpk2(acc2[i][1], c2, c3);
        atomicAdd(&simp[(ty * 4 + i) * 64 + tx * 4 + 0], c0);
        atomicAdd(&simp[(ty * 4 + i) * 64 + tx * 4 + 1], c1);
        atomicAdd(&simp[(ty * 4 + i) * 64 + tx * 4 + 2], c2);
        atomicAdd(&simp[(ty * 4 + i) * 64 + tx * 4 + 3], c3);
    }

    atomicAdd(&g_ssq[bh * 64 + dA + 0], sq0);
    atomicAdd(&g_ssq[bh * 64 + dA + 1], sq1);
    atomicAdd(&g_ssq[bh * 64 + dA + 2], sq2);
    atomicAdd(&g_ssq[bh * 64 + dA + 3], sq3);
    atomicAdd(&g_ssk[bh * 64 + dA + 0], sk0);
    atomicAdd(&g_ssk[bh * 64 + dA + 1], sk1);
    atomicAdd(&g_ssk[bh * 64 + dA + 2], sk2);
    atomicAdd(&g_ssk[bh * 64 + dA + 3], sk3);
}

// ---------------- kernel 3b: scale + softmax over e (256 threads: 64 d x 4 e-groups) --------
__global__ __launch_bounds__(256) void k_softmax(const float* __restrict__ temperature) {
    const int bh = blockIdx.x;
    const int tid = threadIdx.x;
    const int d = tid >> 2;          // 0..63
    const int sub = tid & 3;         // e-group: 16 e's each
    const int h = bh & 15;
    const float tscale = 8.0f * expf(temperature[h]);

    __shared__ float rk[64];
    if (tid < 64) rk[tid] = 1.0f / fmaxf(sqrtf(g_ssk[bh * 64 + tid]), 1e-12f);
    __syncthreads();

    const float rq = 1.0f / fmaxf(sqrtf(g_ssq[bh * 64 + d]), 1e-12f);
    const float* srow = g_sim + bh * 4096 + d * 64 + sub * 16;

    float s[16];
    float mx = -1e30f;
    const float sc = tscale * rq;
    #pragma unroll
    for (int j = 0; j < 16; j++) {
        s[j] = srow[j] * sc * rk[sub * 16 + j];
        mx = fmaxf(mx, s[j]);
    }
    mx = fmaxf(mx, __shfl_xor_sync(0xffffffffu, mx, 1));
    mx = fmaxf(mx, __shfl_xor_sync(0xffffffffu, mx, 2));
    float sum = 0.0f;
    #pragma unroll
    for (int j = 0; j < 16; j++) {
        s[j] = expf(s[j] - mx);
        sum += s[j];
    }
    sum += __shfl_xor_sync(0xffffffffu, sum, 1);
    sum += __shfl_xor_sync(0xffffffffu, sum, 2);
    const float inv = 1.0f / sum;
    float* arow = g_attn + bh * 4096 + d * 64 + sub * 16;
    #pragma unroll
    for (int j = 0; j < 16; j += 4) {
        float4 o = make_float4(s[j] * inv, s[j + 1] * inv, s[j + 2] * inv, s[j + 3] * inv);
        *(float4*)&arow[j] = o;
    }
}

// ---------------- kernel 3c: M_b[(h,e), j] = sum_d attn[b,h,d,e] * w_out[(h,d), j] ----------
__global__ __launch_bounds__(256) void k_M(const float* __restrict__ W) {
    const int bh = blockIdx.x;
    const int j0 = blockIdx.y * 128;
    const int b = bh >> 4, h = bh & 15;
    const int tid = threadIdx.x;
    const int tx = tid & 15, ty = tid >> 4;

    __shared__ float am[64][64];    // am[d][e]
    __shared__ float ws[64][132];   // ws[d][jj]

    const float4* ap4 = (const float4*)(g_attn + bh * 4096);
    #pragma unroll
    for (int i = 0; i < 4; i++)
        ((float4*)am)[tid + i * 256] = ap4[tid + i * 256];
    #pragma unroll
    for (int i = 0; i < 8; i++) {
        int idx = tid + i * 256;
        int d = idx >> 5, jj = (idx & 31) * 4;
        *(float4*)&ws[d][jj] = *(const float4*)&W[(size_t)(h * 64 + d) * DI + j0 + jj];
    }
    __syncthreads();

    float acc[4][8];
    #pragma unroll
    for (int i = 0; i < 4; i++)
        #pragma unroll
        for (int j = 0; j < 8; j++) acc[i][j] = 0.0f;

    #pragma unroll 8
    for (int d = 0; d < 64; d++) {
        float4 a4 = *(const float4*)&am[d][ty * 4];
        float4 b0 = *(const float4*)&ws[d][tx * 8];
        float4 b1 = *(const float4*)&ws[d][tx * 8 + 4];
        float aa[4] = {a4.x, a4.y, a4.z, a4.w};
        float bb[8] = {b0.x, b0.y, b0.z, b0.w, b1.x, b1.y, b1.z, b1.w};
        #pragma unroll
        for (int i = 0; i < 4; i++)
            #pragma unroll
            for (int j = 0; j < 8; j++)
                acc[i][j] = fmaf(aa[i], bb[j], acc[i][j]);
    }

    #pragma unroll
    for (int i = 0; i < 4; i++) {
        int he = h * 64 + ty * 4 + i;
        float* mrow = g_M + ((size_t)b * DI + he) * DI + j0 + tx * 8;
        *(float4*)mrow       = make_float4(acc[i][0], acc[i][1], acc[i][2], acc[i][3]);
        *(float4*)(mrow + 4) = make_float4(acc[i][4], acc[i][5], acc[i][6], acc[i][7]);
    }
}

// ---------------- launch ----------------
extern "C" void kernel_launch(void* const* d_in, const int* in_sizes, int n_in,
                              void* d_out, int out_size) {
    const float* x = (const float*)d_in[0];
    const float* gamma = (const float*)d_in[1];
    const float* w_qkv = (const float*)d_in[2];
    const float* temperature = (const float*)d_in[3];
    const float* w_out = (const float*)d_in[4];
    float* out = (float*)d_out;

    k_wfold<<<(DIMX * QKVN / 4) / 256, 256>>>(w_qkv, gamma);
    k_rscale<<<MROWS, 256>>>(x);
    k_gemm_qkv<<<dim3(QKVN / 128, MROWS / 128), 256>>>(x);
    k_sim<<<dim3(64, 16), 256>>>();
    k_softmax<<<64, 256>>>(temperature);
    k_M<<<dim3(64, 8), 256>>>(w_out);
    k_gemm_out<<<dim3(DI / 128, MROWS / 128), 256>>>(out);
}

// round 14
// speedup vs baseline: 1.1850x; 1.0041x over previous
#include <cuda_runtime.h>
#include <math.h>

// ---------------- problem constants ----------------
#define BQ     4
#define SEQ    4096
#define DIMX   1024
#define HEADS  16
#define DH     64
#define DI     1024
#define MROWS  (BQ*SEQ)     // 16384
#define QKVN   3072

typedef unsigned long long u64;

// ---------------- scratch (device globals; no allocation) ----------------
__device__ float g_q  [(size_t)MROWS * DI];     //  64 MB
__device__ float g_k  [(size_t)MROWS * DI];     //  64 MB
__device__ float g_v  [(size_t)MROWS * DI];     //  64 MB
__device__ float g_wq [(size_t)DIMX * QKVN];    //  12 MB: gamma-folded w_qkv
__device__ float g_rs [MROWS];                  // per-row rmsnorm scale
__device__ float g_M  [(size_t)BQ * DI * DI];   //  16 MB: per-batch M_b
__device__ float g_sim [64 * 64 * 64];          // raw Gram per (b,h)
__device__ float g_attn[64 * 64 * 64];
__device__ float g_ssq[64 * 64];                // sum q^2 per (bh, d)
__device__ float g_ssk[64 * 64];                // sum k^2 per (bh, e)

// ---------------- f32x2 helpers ----------------
__device__ __forceinline__ u64 pk2(float lo, float hi) {
    u64 r;
    asm("mov.b64 %0, {%1, %2};" : "=l"(r)
        : "r"(__float_as_uint(lo)), "r"(__float_as_uint(hi)));
    return r;
}
__device__ __forceinline__ u64 pkdup(float v) {
    u64 r;
    asm("mov.b64 %0, {%1, %1};" : "=l"(r) : "r"(__float_as_uint(v)));
    return r;
}
__device__ __forceinline__ void unpk2(u64 u, float& lo, float& hi) {
    unsigned int a, b;
    asm("mov.b64 {%0, %1}, %2;" : "=r"(a), "=r"(b) : "l"(u));
    lo = __uint_as_float(a);
    hi = __uint_as_float(b);
}
#define FFMA2(c, a, b) asm("fma.rn.f32x2 %0, %1, %2, %0;" : "+l"(c) : "l"(a), "l"(b))

// ---------------- kernel 0a: fold gamma into w_qkv rows ----------------
__global__ __launch_bounds__(256) void k_wfold(const float* __restrict__ w,
                                               const float* __restrict__ gamma) {
    int idx = blockIdx.x * 256 + threadIdx.x;          // float4 index
    int row = idx / (QKVN / 4);
    float g = gamma[row];
    float4 v = ((const float4*)w)[idx];
    v.x *= g; v.y *= g; v.z *= g; v.w *= g;
    ((float4*)g_wq)[idx] = v;
}

// ---------------- kernel 0b: row scales (+ folded accumulator zeroing) ----------------
__global__ __launch_bounds__(256) void k_rscale(const float* __restrict__ x) {
    int row = blockIdx.x;
    int t = threadIdx.x;

    if (row < 1024) {
        int i = row * 256 + t;
        if (i < 64 * 64 * 64) g_sim[i] = 0.0f;
        if (i < 64 * 64) { g_ssq[i] = 0.0f; g_ssk[i] = 0.0f; }
    }

    float4 v = ((const float4*)(x + (size_t)row * DIMX))[t];
    float ss = v.x * v.x + v.y * v.y + v.z * v.z + v.w * v.w;
    __shared__ float red[8];
    #pragma unroll
    for (int o = 16; o; o >>= 1) ss += __shfl_xor_sync(0xffffffffu, ss, o);
    if ((t & 31) == 0) red[t >> 5] = ss;
    __syncthreads();
    if (t < 8) {
        float s2 = red[t];
        #pragma unroll
        for (int o = 4; o; o >>= 1) s2 += __shfl_xor_sync(0xffu, s2, o);
        if (t == 0) g_rs[row] = 32.0f / fmaxf(sqrtf(s2), 1e-12f);
    }
}

// ---------------- GEMM body (proven core; separate B-col and C targets) ----------------
// BN = width of B matrix; C written at (row, ccol0..) with row stride 1024.
#define ASTRIDE 132
template <int BN, bool RSCALE>
__device__ __forceinline__ void gemm_body(const float* __restrict__ A,
                                          const float* __restrict__ Bm,
                                          float* __restrict__ C,
                                          const float* __restrict__ rs,
                                          int bcol0, int ccol0) {
    constexpr int K = 1024;
    __shared__ float As[2][16][ASTRIDE];
    __shared__ float Bs[2][16][128];

    const int tid = threadIdx.x;
    const int tx = tid & 15;
    const int ty = tid >> 4;
    const int row0 = blockIdx.y * 128;

    const int ar = tid >> 2;          // 0..63 (second load covers 64..127)
    const int ak = (tid & 3) * 4;     // 0,4,8,12
    const int bk = tid >> 5;          // 0..7  (second load covers 8..15)
    const int bn = (tid & 31) * 4;    // 0..124

    const float* Aptr = A + (size_t)(row0 + ar) * K + ak;
    const float* Bptr = Bm + (size_t)bk * BN + bcol0 + bn;

    u64 acc[8][4];
    #pragma unroll
    for (int i = 0; i < 8; i++)
        #pragma unroll
        for (int j = 0; j < 4; j++) acc[i][j] = 0ull;

    float4 a0 = *(const float4*)Aptr;
    float4 a1 = *(const float4*)(Aptr + (size_t)64 * K);
    float4 b0 = *(const float4*)Bptr;
    float4 b1 = *(const float4*)(Bptr + (size_t)8 * BN);

    As[0][ak + 0][ar] = a0.x; As[0][ak + 1][ar] = a0.y;
    As[0][ak + 2][ar] = a0.z; As[0][ak + 3][ar] = a0.w;
    As[0][ak + 0][64 + ar] = a1.x; As[0][ak + 1][64 + ar] = a1.y;
    As[0][ak + 2][64 + ar] = a1.z; As[0][ak + 3][64 + ar] = a1.w;
    *(float4*)&Bs[0][bk][bn] = b0;
    *(float4*)&Bs[0][bk + 8][bn] = b1;
    __syncthreads();

    const int NT = K / 16;
    for (int t = 0; t < NT; t++) {
        const int cur = t & 1;
        if (t + 1 < NT) {
            const float* Ap = A + (size_t)(row0 + ar) * K + (t + 1) * 16 + ak;
            a0 = *(const float4*)Ap;
            a1 = *(const float4*)(Ap + (size_t)64 * K);
            const float* Bp = Bm + (size_t)((t + 1) * 16 + bk) * BN + bcol0 + bn;
            b0 = *(const float4*)Bp;
            b1 = *(const float4*)(Bp + (size_t)8 * BN);
        }
        #pragma unroll
        for (int k = 0; k < 16; k++) {
            float4 av0 = *(const float4*)&As[cur][k][ty * 4];
            float4 av1 = *(const float4*)&As[cur][k][64 + ty * 4];
            float4 bv0 = *(const float4*)&Bs[cur][k][tx * 4];
            float4 bv1 = *(const float4*)&Bs[cur][k][64 + tx * 4];
            u64 bp0 = pk2(bv0.x, bv0.y), bp1 = pk2(bv0.z, bv0.w);
            u64 bp2 = pk2(bv1.x, bv1.y), bp3 = pk2(bv1.z, bv1.w);
            float a[8] = {av0.x, av0.y, av0.z, av0.w, av1.x, av1.y, av1.z, av1.w};
            #pragma unroll
            for (int i = 0; i < 8; i++) {
                u64 ap = pkdup(a[i]);
                FFMA2(acc[i][0], ap, bp0);
                FFMA2(acc[i][1], ap, bp1);
                FFMA2(acc[i][2], ap, bp2);
                FFMA2(acc[i][3], ap, bp3);
            }
        }
        if (t + 1 < NT) {
            // single-barrier double buffering
            const int nxt = cur ^ 1;
            As[nxt][ak + 0][ar] = a0.x; As[nxt][ak + 1][ar] = a0.y;
            As[nxt][ak + 2][ar] = a0.z; As[nxt][ak + 3][ar] = a0.w;
            As[nxt][ak + 0][64 + ar] = a1.x; As[nxt][ak + 1][64 + ar] = a1.y;
            As[nxt][ak + 2][64 + ar] = a1.z; As[nxt][ak + 3][64 + ar] = a1.w;
            *(float4*)&Bs[nxt][bk][bn] = b0;
            *(float4*)&Bs[nxt][bk + 8][bn] = b1;
            __syncthreads();
        }
    }

    #pragma unroll
    for (int i = 0; i < 8; i++) {
        int r = row0 + ((i < 4) ? (ty * 4 + i) : (64 + ty * 4 + i - 4));
        float x0, x1, x2, x3, x4, x5, x6, x7;
        unpk2(acc[i][0], x0, x1);
        unpk2(acc[i][1], x2, x3);
        unpk2(acc[i][2], x4, x5);
        unpk2(acc[i][3], x6, x7);
        if (RSCALE) {
            float s = rs[r];
            x0 *= s; x1 *= s; x2 *= s; x3 *= s;
            x4 *= s; x5 *= s; x6 *= s; x7 *= s;
        }
        float4 o0 = make_float4(x0, x1, x2, x3);
        float4 o1 = make_float4(x4, x5, x6, x7);
        *(float4*)&C[(size_t)r * DI + ccol0 + tx * 4] = o0;
        *(float4*)&C[(size_t)r * DI + ccol0 + 64 + tx * 4] = o1;
    }
}

// GEMM1: qkv = (x*rs) @ w'; output split into compact q/k/v planes by column block.
__global__ __launch_bounds__(256, 2) void k_gemm_qkv(const float* __restrict__ x) {
    const int cb = blockIdx.x;                 // 0..23
    float* C;
    int ccol0;
    if (cb < 8)       { C = g_q; ccol0 = cb * 128; }
    else if (cb < 16) { C = g_k; ccol0 = (cb - 8) * 128; }
    else              { C = g_v; ccol0 = (cb - 16) * 128; }
    gemm_body<QKVN, true>(x, g_wq, C, g_rs, cb * 128, ccol0);
}
// GEMM2: out = v @ per-batch M (dense stride-1024 A).
__global__ __launch_bounds__(256, 2) void k_gemm_out(float* __restrict__ out) {
    const float* Mb = g_M + (size_t)(blockIdx.y >> 5) * DI * DI;
    gemm_body<DI, false>(g_v, Mb, out, nullptr, blockIdx.x * 128, blockIdx.x * 128);
}

// ---------------- kernel 3a: raw Gram sim += q.k over n-split; FFMA2-packed ----------------
__global__ __launch_bounds__(256) void k_sim() {
    const int bh = blockIdx.x;        // b*16 + h
    const int split = blockIdx.y;     // 0..15, 256 n each
    const int b = bh >> 4, h = bh & 15;
    const int tid = threadIdx.x;
    const int tx = tid & 15, ty = tid >> 4;

    __shared__ float qs[32][64];
    __shared__ float ks[32][64];

    u64 acc2[4][2];
    #pragma unroll
    for (int i = 0; i < 4; i++) { acc2[i][0] = 0ull; acc2[i][1] = 0ull; }

    float sq0 = 0, sq1 = 0, sq2 = 0, sq3 = 0;
    float sk0 = 0, sk1 = 0, sk2 = 0, sk3 = 0;

    const size_t basep = ((size_t)b * SEQ) * DI + (size_t)h * DH;
    const int nnA = tid >> 4;          // 0..15
    const int dA = (tid & 15) * 4;     // 0..60

    for (int t = 0; t < 8; t++) {
        const int n = split * 256 + t * 32;
        const float* qg = g_q + basep + (size_t)n * DI;
        const float* kg = g_k + basep + (size_t)n * DI;

        float4 q0 = *(const float4*)(qg + (size_t)nnA * DI + dA);
        float4 q1 = *(const float4*)(qg + (size_t)(nnA + 16) * DI + dA);
        float4 k0 = *(const float4*)(kg + (size_t)nnA * DI + dA);
        float4 k1 = *(const float4*)(kg + (size_t)(nnA + 16) * DI + dA);

        sq0 += q0.x * q0.x + q1.x * q1.x;
        sq1 += q0.y * q0.y + q1.y * q1.y;
        sq2 += q0.z * q0.z + q1.z * q1.z;
        sq3 += q0.w * q0.w + q1.w * q1.w;
        sk0 += k0.x * k0.x + k1.x * k1.x;
        sk1 += k0.y * k0.y + k1.y * k1.y;
        sk2 += k0.z * k0.z + k1.z * k1.z;
        sk3 += k0.w * k0.w + k1.w * k1.w;

        __syncthreads();
        *(float4*)&qs[nnA][dA] = q0;
        *(float4*)&qs[nnA + 16][dA] = q1;
        *(float4*)&ks[nnA][dA] = k0;
        *(float4*)&ks[nnA + 16][dA] = k1;
        __syncthreads();

        #pragma unroll 8
        for (int nn = 0; nn < 32; nn++) {
            float4 qa = *(const float4*)&qs[nn][ty * 4];
            float4 kb = *(const float4*)&ks[nn][tx * 4];
            u64 b01 = pk2(kb.x, kb.y), b23 = pk2(kb.z, kb.w);
            float aa[4] = {qa.x, qa.y, qa.z, qa.w};
            #pragma unroll
            for (int i = 0; i < 4; i++) {
                u64 ad = pkdup(aa[i]);
                FFMA2(acc2[i][0], ad, b01);
                FFMA2(acc2[i][1], ad, b23);
            }
        }
    }

    float* simp = g_sim + bh * 4096;
    #pragma unroll
    for (int i = 0; i < 4; i++) {
        float c0, c1, c2, c3;
        unpk2(acc2[i][0], c0, c1);
        unpk2(acc2[i][1], c2, c3);
        atomicAdd(&simp[(ty * 4 + i) * 64 + tx * 4 + 0], c0);
        atomicAdd(&simp[(ty * 4 + i) * 64 + tx * 4 + 1], c1);
        atomicAdd(&simp[(ty * 4 + i) * 64 + tx * 4 + 2], c2);
        atomicAdd(&simp[(ty * 4 + i) * 64 + tx * 4 + 3], c3);
    }

    atomicAdd(&g_ssq[bh * 64 + dA + 0], sq0);
    atomicAdd(&g_ssq[bh * 64 + dA + 1], sq1);
    atomicAdd(&g_ssq[bh * 64 + dA + 2], sq2);
    atomicAdd(&g_ssq[bh * 64 + dA + 3], sq3);
    atomicAdd(&g_ssk[bh * 64 + dA + 0], sk0);
    atomicAdd(&g_ssk[bh * 64 + dA + 1], sk1);
    atomicAdd(&g_ssk[bh * 64 + dA + 2], sk2);
    atomicAdd(&g_ssk[bh * 64 + dA + 3], sk3);
}

// ---------------- kernel 3b: scale + softmax over e (256 threads: 64 d x 4 e-groups) --------
__global__ __launch_bounds__(256) void k_softmax(const float* __restrict__ temperature) {
    const int bh = blockIdx.x;
    const int tid = threadIdx.x;
    const int d = tid >> 2;          // 0..63
    const int sub = tid & 3;         // e-group: 16 e's each
    const int h = bh & 15;
    const float tscale = 8.0f * expf(temperature[h]);

    __shared__ float rk[64];
    if (tid < 64) rk[tid] = 1.0f / fmaxf(sqrtf(g_ssk[bh * 64 + tid]), 1e-12f);
    __syncthreads();

    const float rq = 1.0f / fmaxf(sqrtf(g_ssq[bh * 64 + d]), 1e-12f);
    const float* srow = g_sim + bh * 4096 + d * 64 + sub * 16;

    float s[16];
    float mx = -1e30f;
    const float sc = tscale * rq;
    #pragma unroll
    for (int j = 0; j < 16; j++) {
        s[j] = srow[j] * sc * rk[sub * 16 + j];
        mx = fmaxf(mx, s[j]);
    }
    mx = fmaxf(mx, __shfl_xor_sync(0xffffffffu, mx, 1));
    mx = fmaxf(mx, __shfl_xor_sync(0xffffffffu, mx, 2));
    float sum = 0.0f;
    #pragma unroll
    for (int j = 0; j < 16; j++) {
        s[j] = expf(s[j] - mx);
        sum += s[j];
    }
    sum += __shfl_xor_sync(0xffffffffu, sum, 1);
    sum += __shfl_xor_sync(0xffffffffu, sum, 2);
    const float inv = 1.0f / sum;
    float* arow = g_attn + bh * 4096 + d * 64 + sub * 16;
    #pragma unroll
    for (int j = 0; j < 16; j += 4) {
        float4 o = make_float4(s[j] * inv, s[j + 1] * inv, s[j + 2] * inv, s[j + 3] * inv);
        *(float4*)&arow[j] = o;
    }
}

// ---------------- kernel 3c: M_b[(h,e), j] = sum_d attn[b,h,d,e] * w_out[(h,d), j] ----------
__global__ __launch_bounds__(256) void k_M(const float* __restrict__ W) {
    const int bh = blockIdx.x;
    const int j0 = blockIdx.y * 128;
    const int b = bh >> 4, h = bh & 15;
    const int tid = threadIdx.x;
    const int tx = tid & 15, ty = tid >> 4;

    __shared__ float am[64][64];    // am[d][e]
    __shared__ float ws[64][132];   // ws[d][jj]

    const float4* ap4 = (const float4*)(g_attn + bh * 4096);
    #pragma unroll
    for (int i = 0; i < 4; i++)
        ((float4*)am)[tid + i * 256] = ap4[tid + i * 256];
    #pragma unroll
    for (int i = 0; i < 8; i++) {
        int idx = tid + i * 256;
        int d = idx >> 5, jj = (idx & 31) * 4;
        *(float4*)&ws[d][jj] = *(const float4*)&W[(size_t)(h * 64 + d) * DI + j0 + jj];
    }
    __syncthreads();

    float acc[4][8];
    #pragma unroll
    for (int i = 0; i < 4; i++)
        #pragma unroll
        for (int j = 0; j < 8; j++) acc[i][j] = 0.0f;

    #pragma unroll 8
    for (int d = 0; d < 64; d++) {
        float4 a4 = *(const float4*)&am[d][ty * 4];
        float4 b0 = *(const float4*)&ws[d][tx * 8];
        float4 b1 = *(const float4*)&ws[d][tx * 8 + 4];
        float aa[4] = {a4.x, a4.y, a4.z, a4.w};
        float bb[8] = {b0.x, b0.y, b0.z, b0.w, b1.x, b1.y, b1.z, b1.w};
        #pragma unroll
        for (int i = 0; i < 4; i++)
            #pragma unroll
            for (int j = 0; j < 8; j++)
                acc[i][j] = fmaf(aa[i], bb[j], acc[i][j]);
    }

    #pragma unroll
    for (int i = 0; i < 4; i++) {
        int he = h * 64 + ty * 4 + i;
        float* mrow = g_M + ((size_t)b * DI + he) * DI + j0 + tx * 8;
        *(float4*)mrow       = make_float4(acc[i][0], acc[i][1], acc[i][2], acc[i][3]);
        *(float4*)(mrow + 4) = make_float4(acc[i][4], acc[i][5], acc[i][6], acc[i][7]);
    }
}

// ---------------- launch ----------------
extern "C" void kernel_launch(void* const* d_in, const int* in_sizes, int n_in,
                              void* d_out, int out_size) {
    const float* x = (const float*)d_in[0];
    const float* gamma = (const float*)d_in[1];
    const float* w_qkv = (const float*)d_in[2];
    const float* temperature = (const float*)d_in[3];
    const float* w_out = (const float*)d_in[4];
    float* out = (float*)d_out;

    k_wfold<<<(DIMX * QKVN / 4) / 256, 256>>>(w_qkv, gamma);
    k_rscale<<<MROWS, 256>>>(x);
    k_gemm_qkv<<<dim3(QKVN / 128, MROWS / 128), 256>>>(x);
    k_sim<<<dim3(64, 16), 256>>>();
    k_softmax<<<64, 256>>>(temperature);
    k_M<<<dim3(64, 8), 256>>>(w_out);
    k_gemm_out<<<dim3(DI / 128, MROWS / 128), 256>>>(out);
}

// round 15
// speedup vs baseline: 1.1854x; 1.0004x over previous
#include <cuda_runtime.h>
#include <math.h>

// ---------------- problem constants ----------------
#define BQ     4
#define SEQ    4096
#define DIMX   1024
#define HEADS  16
#define DH     64
#define DI     1024
#define MROWS  (BQ*SEQ)     // 16384
#define QKVN   3072

typedef unsigned long long u64;

// ---------------- scratch (device globals; no allocation) ----------------
__device__ float g_q  [(size_t)MROWS * DI];     //  64 MB
__device__ float g_k  [(size_t)MROWS * DI];     //  64 MB
__device__ float g_v  [(size_t)MROWS * DI];     //  64 MB
__device__ float g_wq [(size_t)DIMX * QKVN];    //  12 MB: gamma-folded w_qkv
__device__ float g_rs [MROWS];                  // per-row rmsnorm scale
__device__ float g_M  [(size_t)BQ * DI * DI];   //  16 MB: per-batch M_b
__device__ float g_sim [64 * 64 * 64];          // raw Gram per (b,h)
__device__ float g_attn[64 * 64 * 64];
__device__ float g_ssq[64 * 64];                // sum q^2 per (bh, d)
__device__ float g_ssk[64 * 64];                // sum k^2 per (bh, e)

// ---------------- f32x2 helpers ----------------
__device__ __forceinline__ u64 pk2(float lo, float hi) {
    u64 r;
    asm("mov.b64 %0, {%1, %2};" : "=l"(r)
        : "r"(__float_as_uint(lo)), "r"(__float_as_uint(hi)));
    return r;
}
__device__ __forceinline__ u64 pkdup(float v) {
    u64 r;
    asm("mov.b64 %0, {%1, %1};" : "=l"(r) : "r"(__float_as_uint(v)));
    return r;
}
__device__ __forceinline__ void unpk2(u64 u, float& lo, float& hi) {
    unsigned int a, b;
    asm("mov.b64 {%0, %1}, %2;" : "=r"(a), "=r"(b) : "l"(u));
    lo = __uint_as_float(a);
    hi = __uint_as_float(b);
}
#define FFMA2(c, a, b) asm("fma.rn.f32x2 %0, %1, %2, %0;" : "+l"(c) : "l"(a), "l"(b))

// ---------------- kernel 0a: fold gamma into w_qkv rows ----------------
__global__ __launch_bounds__(256) void k_wfold(const float* __restrict__ w,
                                               const float* __restrict__ gamma) {
    int idx = blockIdx.x * 256 + threadIdx.x;          // float4 index
    int row = idx / (QKVN / 4);
    float g = gamma[row];
    float4 v = ((const float4*)w)[idx];
    v.x *= g; v.y *= g; v.z *= g; v.w *= g;
    ((float4*)g_wq)[idx] = v;
}

// ---------------- kernel 0b: row scales (+ folded accumulator zeroing) ----------------
__global__ __launch_bounds__(256) void k_rscale(const float* __restrict__ x) {
    int row = blockIdx.x;
    int t = threadIdx.x;

    if (row < 1024) {
        int i = row * 256 + t;
        if (i < 64 * 64 * 64) g_sim[i] = 0.0f;
        if (i < 64 * 64) { g_ssq[i] = 0.0f; g_ssk[i] = 0.0f; }
    }

    float4 v = ((const float4*)(x + (size_t)row * DIMX))[t];
    float ss = v.x * v.x + v.y * v.y + v.z * v.z + v.w * v.w;
    __shared__ float red[8];
    #pragma unroll
    for (int o = 16; o; o >>= 1) ss += __shfl_xor_sync(0xffffffffu, ss, o);
    if ((t & 31) == 0) red[t >> 5] = ss;
    __syncthreads();
    if (t < 8) {
        float s2 = red[t];
        #pragma unroll
        for (int o = 4; o; o >>= 1) s2 += __shfl_xor_sync(0xffu, s2, o);
        if (t == 0) g_rs[row] = 32.0f / fmaxf(sqrtf(s2), 1e-12f);
    }
}

// ---------------- GEMM body (proven core; separate B-col and C targets) ----------------
#define ASTRIDE 132
template <int BN, bool RSCALE>
__device__ __forceinline__ void gemm_body(const float* __restrict__ A,
                                          const float* __restrict__ Bm,
                                          float* __restrict__ C,
                                          const float* __restrict__ rs,
                                          int bcol0, int ccol0) {
    constexpr int K = 1024;
    __shared__ float As[2][16][ASTRIDE];
    __shared__ float Bs[2][16][128];

    const int tid = threadIdx.x;
    const int tx = tid & 15;
    const int ty = tid >> 4;
    const int row0 = blockIdx.y * 128;

    const int ar = tid >> 2;          // 0..63 (second load covers 64..127)
    const int ak = (tid & 3) * 4;     // 0,4,8,12
    const int bk = tid >> 5;          // 0..7  (second load covers 8..15)
    const int bn = (tid & 31) * 4;    // 0..124

    const float* Aptr = A + (size_t)(row0 + ar) * K + ak;
    const float* Bptr = Bm + (size_t)bk * BN + bcol0 + bn;

    u64 acc[8][4];
    #pragma unroll
    for (int i = 0; i < 8; i++)
        #pragma unroll
        for (int j = 0; j < 4; j++) acc[i][j] = 0ull;

    float4 a0 = *(const float4*)Aptr;
    float4 a1 = *(const float4*)(Aptr + (size_t)64 * K);
    float4 b0 = *(const float4*)Bptr;
    float4 b1 = *(const float4*)(Bptr + (size_t)8 * BN);

    As[0][ak + 0][ar] = a0.x; As[0][ak + 1][ar] = a0.y;
    As[0][ak + 2][ar] = a0.z; As[0][ak + 3][ar] = a0.w;
    As[0][ak + 0][64 + ar] = a1.x; As[0][ak + 1][64 + ar] = a1.y;
    As[0][ak + 2][64 + ar] = a1.z; As[0][ak + 3][64 + ar] = a1.w;
    *(float4*)&Bs[0][bk][bn] = b0;
    *(float4*)&Bs[0][bk + 8][bn] = b1;
    __syncthreads();

    const int NT = K / 16;
    for (int t = 0; t < NT; t++) {
        const int cur = t & 1;
        if (t + 1 < NT) {
            const float* Ap = A + (size_t)(row0 + ar) * K + (t + 1) * 16 + ak;
            a0 = *(const float4*)Ap;
            a1 = *(const float4*)(Ap + (size_t)64 * K);
            const float* Bp = Bm + (size_t)((t + 1) * 16 + bk) * BN + bcol0 + bn;
            b0 = *(const float4*)Bp;
            b1 = *(const float4*)(Bp + (size_t)8 * BN);
        }
        #pragma unroll
        for (int k = 0; k < 16; k++) {
            float4 av0 = *(const float4*)&As[cur][k][ty * 4];
            float4 av1 = *(const float4*)&As[cur][k][64 + ty * 4];
            float4 bv0 = *(const float4*)&Bs[cur][k][tx * 4];
            float4 bv1 = *(const float4*)&Bs[cur][k][64 + tx * 4];
            u64 bp0 = pk2(bv0.x, bv0.y), bp1 = pk2(bv0.z, bv0.w);
            u64 bp2 = pk2(bv1.x, bv1.y), bp3 = pk2(bv1.z, bv1.w);
            float a[8] = {av0.x, av0.y, av0.z, av0.w, av1.x, av1.y, av1.z, av1.w};
            #pragma unroll
            for (int i = 0; i < 8; i++) {
                u64 ap = pkdup(a[i]);
                FFMA2(acc[i][0], ap, bp0);
                FFMA2(acc[i][1], ap, bp1);
                FFMA2(acc[i][2], ap, bp2);
                FFMA2(acc[i][3], ap, bp3);
            }
        }
        if (t + 1 < NT) {
            // single-barrier double buffering
            const int nxt = cur ^ 1;
            As[nxt][ak + 0][ar] = a0.x; As[nxt][ak + 1][ar] = a0.y;
            As[nxt][ak + 2][ar] = a0.z; As[nxt][ak + 3][ar] = a0.w;
            As[nxt][ak + 0][64 + ar] = a1.x; As[nxt][ak + 1][64 + ar] = a1.y;
            As[nxt][ak + 2][64 + ar] = a1.z; As[nxt][ak + 3][64 + ar] = a1.w;
            *(float4*)&Bs[nxt][bk][bn] = b0;
            *(float4*)&Bs[nxt][bk + 8][bn] = b1;
            __syncthreads();
        }
    }

    #pragma unroll
    for (int i = 0; i < 8; i++) {
        int r = row0 + ((i < 4) ? (ty * 4 + i) : (64 + ty * 4 + i - 4));
        float x0, x1, x2, x3, x4, x5, x6, x7;
        unpk2(acc[i][0], x0, x1);
        unpk2(acc[i][1], x2, x3);
        unpk2(acc[i][2], x4, x5);
        unpk2(acc[i][3], x6, x7);
        if (RSCALE) {
            float s = rs[r];
            x0 *= s; x1 *= s; x2 *= s; x3 *= s;
            x4 *= s; x5 *= s; x6 *= s; x7 *= s;
        }
        float4 o0 = make_float4(x0, x1, x2, x3);
        float4 o1 = make_float4(x4, x5, x6, x7);
        *(float4*)&C[(size_t)r * DI + ccol0 + tx * 4] = o0;
        *(float4*)&C[(size_t)r * DI + ccol0 + 64 + tx * 4] = o1;
    }
}

// GEMM1: qkv = (x*rs) @ w'; output split into compact q/k/v planes by column block.
__global__ __launch_bounds__(256, 2) void k_gemm_qkv(const float* __restrict__ x) {
    const int cb = blockIdx.x;                 // 0..23
    float* C;
    int ccol0;
    if (cb < 8)       { C = g_q; ccol0 = cb * 128; }
    else if (cb < 16) { C = g_k; ccol0 = (cb - 8) * 128; }
    else              { C = g_v; ccol0 = (cb - 16) * 128; }
    gemm_body<QKVN, true>(x, g_wq, C, g_rs, cb * 128, ccol0);
}
// GEMM2: out = v @ per-batch M (dense stride-1024 A).
__global__ __launch_bounds__(256, 2) void k_gemm_out(float* __restrict__ out) {
    const float* Mb = g_M + (size_t)(blockIdx.y >> 5) * DI * DI;
    gemm_body<DI, false>(g_v, Mb, out, nullptr, blockIdx.x * 128, blockIdx.x * 128);
}

// ---------------- kernel 3a: raw Gram sim += q.k over n-split; also sumsq ----------------
// 8d x 4e microtile, 32-nn range split across two 128-thread halves (25% fewer LDS on the
// binding L1 port); halves combined through smem so global atomics halve.
__global__ __launch_bounds__(256) void k_sim() {
    const int bh = blockIdx.x;        // b*16 + h
    const int split = blockIdx.y;     // 0..15, 256 n each
    const int b = bh >> 4, h = bh & 15;
    const int tid = threadIdx.x;
    const int half = tid >> 7;        // 0,1: nn range [half*16, half*16+16)
    const int w128 = tid & 127;
    const int tx = w128 & 15;         // e-group: e = tx*4..+3
    const int tyy = w128 >> 4;        // d-group: d = tyy*8..+7

    __shared__ float qs[32][64];
    __shared__ float ks[32][64];

    u64 acc2[8][2];                   // [d][e-pair]
    #pragma unroll
    for (int i = 0; i < 8; i++) { acc2[i][0] = 0ull; acc2[i][1] = 0ull; }

    float sq0 = 0, sq1 = 0, sq2 = 0, sq3 = 0;
    float sk0 = 0, sk1 = 0, sk2 = 0, sk3 = 0;

    const size_t basep = ((size_t)b * SEQ) * DI + (size_t)h * DH;
    const int nnA = tid >> 4;          // 0..15 (staging rows; +16 for second)
    const int dA = (tid & 15) * 4;     // 0..60

    for (int t = 0; t < 8; t++) {
        const int n = split * 256 + t * 32;
        const float* qg = g_q + basep + (size_t)n * DI;
        const float* kg = g_k + basep + (size_t)n * DI;

        float4 q0 = *(const float4*)(qg + (size_t)nnA * DI + dA);
        float4 q1 = *(const float4*)(qg + (size_t)(nnA + 16) * DI + dA);
        float4 k0 = *(const float4*)(kg + (size_t)nnA * DI + dA);
        float4 k1 = *(const float4*)(kg + (size_t)(nnA + 16) * DI + dA);

        sq0 += q0.x * q0.x + q1.x * q1.x;
        sq1 += q0.y * q0.y + q1.y * q1.y;
        sq2 += q0.z * q0.z + q1.z * q1.z;
        sq3 += q0.w * q0.w + q1.w * q1.w;
        sk0 += k0.x * k0.x + k1.x * k1.x;
        sk1 += k0.y * k0.y + k1.y * k1.y;
        sk2 += k0.z * k0.z + k1.z * k1.z;
        sk3 += k0.w * k0.w + k1.w * k1.w;

        __syncthreads();
        *(float4*)&qs[nnA][dA] = q0;
        *(float4*)&qs[nnA + 16][dA] = q1;
        *(float4*)&ks[nnA][dA] = k0;
        *(float4*)&ks[nnA + 16][dA] = k1;
        __syncthreads();

        const int nn0 = half * 16;
        #pragma unroll 8
        for (int i = 0; i < 16; i++) {
            const int nn = nn0 + i;
            float4 qa0 = *(const float4*)&qs[nn][tyy * 8];
            float4 qa1 = *(const float4*)&qs[nn][tyy * 8 + 4];
            float4 kb  = *(const float4*)&ks[nn][tx * 4];
            u64 b01 = pk2(kb.x, kb.y), b23 = pk2(kb.z, kb.w);
            float aa[8] = {qa0.x, qa0.y, qa0.z, qa0.w, qa1.x, qa1.y, qa1.z, qa1.w};
            #pragma unroll
            for (int d = 0; d < 8; d++) {
                u64 ad = pkdup(aa[d]);
                FFMA2(acc2[d][0], ad, b01);
                FFMA2(acc2[d][1], ad, b23);
            }
        }
    }

    // combine halves through smem (reuse qs/ks as 16 KB scratch), then half-0 atomics
    __syncthreads();
    float* scratch = &qs[0][0];                 // 2048 floats (qs) + 2048 (ks) contiguous? no —
    float* scratch2 = &ks[0][0];                // use both arrays: 2048 + 2048 floats
    if (half == 1) {
        #pragma unroll
        for (int d = 0; d < 8; d++) {
            float c0, c1, c2, c3;
            unpk2(acc2[d][0], c0, c1);
            unpk2(acc2[d][1], c2, c3);
            int base = w128 * 16 + d * 2;       // 128 threads * 16 floats... split across arrays
            // store 4 floats per d: use flat index w128*32 + d*4 over 4096 floats (2 arrays)
            int fi = w128 * 32 + d * 4;
            float* dst = (fi < 2048) ? (scratch + fi) : (scratch2 + fi - 2048);
            dst[0] = c0; dst[1] = c1; dst[2] = c2; dst[3] = c3;
            (void)base;
        }
    }
    __syncthreads();
    if (half == 0) {
        float* simp = g_sim + bh * 4096;
        #pragma unroll
        for (int d = 0; d < 8; d++) {
            float c0, c1, c2, c3;
            unpk2(acc2[d][0], c0, c1);
            unpk2(acc2[d][1], c2, c3);
            int fi = w128 * 32 + d * 4;
            const float* src = (fi < 2048) ? (scratch + fi) : (scratch2 + fi - 2048);
            c0 += src[0]; c1 += src[1]; c2 += src[2]; c3 += src[3];
            int row = (tyy * 8 + d) * 64 + tx * 4;
            atomicAdd(&simp[row + 0], c0);
            atomicAdd(&simp[row + 1], c1);
            atomicAdd(&simp[row + 2], c2);
            atomicAdd(&simp[row + 3], c3);
        }
    }

    atomicAdd(&g_ssq[bh * 64 + dA + 0], sq0);
    atomicAdd(&g_ssq[bh * 64 + dA + 1], sq1);
    atomicAdd(&g_ssq[bh * 64 + dA + 2], sq2);
    atomicAdd(&g_ssq[bh * 64 + dA + 3], sq3);
    atomicAdd(&g_ssk[bh * 64 + dA + 0], sk0);
    atomicAdd(&g_ssk[bh * 64 + dA + 1], sk1);
    atomicAdd(&g_ssk[bh * 64 + dA + 2], sk2);
    atomicAdd(&g_ssk[bh * 64 + dA + 3], sk3);
}

// ---------------- kernel 3b: scale + softmax over e (256 threads: 64 d x 4 e-groups) --------
__global__ __launch_bounds__(256) void k_softmax(const float* __restrict__ temperature) {
    const int bh = blockIdx.x;
    const int tid = threadIdx.x;
    const int d = tid >> 2;          // 0..63
    const int sub = tid & 3;         // e-group: 16 e's each
    const int h = bh & 15;
    const float tscale = 8.0f * expf(temperature[h]);

    __shared__ float rk[64];
    if (tid < 64) rk[tid] = 1.0f / fmaxf(sqrtf(g_ssk[bh * 64 + tid]), 1e-12f);
    __syncthreads();

    const float rq = 1.0f / fmaxf(sqrtf(g_ssq[bh * 64 + d]), 1e-12f);
    const float* srow = g_sim + bh * 4096 + d * 64 + sub * 16;

    float s[16];
    float mx = -1e30f;
    const float sc = tscale * rq;
    #pragma unroll
    for (int j = 0; j < 16; j++) {
        s[j] = srow[j] * sc * rk[sub * 16 + j];
        mx = fmaxf(mx, s[j]);
    }
    mx = fmaxf(mx, __shfl_xor_sync(0xffffffffu, mx, 1));
    mx = fmaxf(mx, __shfl_xor_sync(0xffffffffu, mx, 2));
    float sum = 0.0f;
    #pragma unroll
    for (int j = 0; j < 16; j++) {
        s[j] = expf(s[j] - mx);
        sum += s[j];
    }
    sum += __shfl_xor_sync(0xffffffffu, sum, 1);
    sum += __shfl_xor_sync(0xffffffffu, sum, 2);
    const float inv = 1.0f / sum;
    float* arow = g_attn + bh * 4096 + d * 64 + sub * 16;
    #pragma unroll
    for (int j = 0; j < 16; j += 4) {
        float4 o = make_float4(s[j] * inv, s[j + 1] * inv, s[j + 2] * inv, s[j + 3] * inv);
        *(float4*)&arow[j] = o;
    }
}

// ---------------- kernel 3c: M_b[(h,e), j] = sum_d attn[b,h,d,e] * w_out[(h,d), j] ----------
__global__ __launch_bounds__(256) void k_M(const float* __restrict__ W) {
    const int bh = blockIdx.x;
    const int j0 = blockIdx.y * 128;
    const int b = bh >> 4, h = bh & 15;
    const int tid = threadIdx.x;
    const int tx = tid & 15, ty = tid >> 4;

    __shared__ float am[64][64];    // am[d][e]
    __shared__ float ws[64][132];   // ws[d][jj]

    const float4* ap4 = (const float4*)(g_attn + bh * 4096);
    #pragma unroll
    for (int i = 0; i < 4; i++)
        ((float4*)am)[tid + i * 256] = ap4[tid + i * 256];
    #pragma unroll
    for (int i = 0; i < 8; i++) {
        int idx = tid + i * 256;
        int d = idx >> 5, jj = (idx & 31) * 4;
        *(float4*)&ws[d][jj] = *(const float4*)&W[(size_t)(h * 64 + d) * DI + j0 + jj];
    }
    __syncthreads();

    float acc[4][8];
    #pragma unroll
    for (int i = 0; i < 4; i++)
        #pragma unroll
        for (int j = 0; j < 8; j++) acc[i][j] = 0.0f;

    #pragma unroll 8
    for (int d = 0; d < 64; d++) {
        float4 a4 = *(const float4*)&am[d][ty * 4];
        float4 b0 = *(const float4*)&ws[d][tx * 8];
        float4 b1 = *(const float4*)&ws[d][tx * 8 + 4];
        float aa[4] = {a4.x, a4.y, a4.z, a4.w};
        float bb[8] = {b0.x, b0.y, b0.z, b0.w, b1.x, b1.y, b1.z, b1.w};
        #pragma unroll
        for (int i = 0; i < 4; i++)
            #pragma unroll
            for (int j = 0; j < 8; j++)
                acc[i][j] = fmaf(aa[i], bb[j], acc[i][j]);
    }

    #pragma unroll
    for (int i = 0; i < 4; i++) {
        int he = h * 64 + ty * 4 + i;
        float* mrow = g_M + ((size_t)b * DI + he) * DI + j0 + tx * 8;
        *(float4*)mrow       = make_float4(acc[i][0], acc[i][1], acc[i][2], acc[i][3]);
        *(float4*)(mrow + 4) = make_float4(acc[i][4], acc[i][5], acc[i][6], acc[i][7]);
    }
}

// ---------------- launch ----------------
extern "C" void kernel_launch(void* const* d_in, const int* in_sizes, int n_in,
                              void* d_out, int out_size) {
    const float* x = (const float*)d_in[0];
    const float* gamma = (const float*)d_in[1];
    const float* w_qkv = (const float*)d_in[2];
    const float* temperature = (const float*)d_in[3];
    const float* w_out = (const float*)d_in[4];
    float* out = (float*)d_out;

    k_wfold<<<(DIMX * QKVN / 4) / 256, 256>>>(w_qkv, gamma);
    k_rscale<<<MROWS, 256>>>(x);
    k_gemm_qkv<<<dim3(QKVN / 128, MROWS / 128), 256>>>(x);
    k_sim<<<dim3(64, 16), 256>>>();
    k_softmax<<<64, 256>>>(temperature);
    k_M<<<dim3(64, 8), 256>>>(w_out);
    k_gemm_out<<<dim3(DI / 128, MROWS / 128), 256>>>(out);
}

// round 16
// speedup vs baseline: 1.4411x; 1.2157x over previous
#include <cuda_runtime.h>
#include <math.h>

// ---------------- problem constants ----------------
#define BQ     4
#define SEQ    4096
#define DIMX   1024
#define HEADS  16
#define DH     64
#define DI     1024
#define MROWS  (BQ*SEQ)     // 16384
#define QKVN   3072

typedef unsigned long long u64;

// ---------------- scratch (device globals; no allocation) ----------------
__device__ float g_wqp[(size_t)DIMX * DI];      // 4 MB: gamma-folded Wq
__device__ float g_wk [(size_t)DIMX * DI];      // 4 MB: gamma-folded Wk
__device__ float g_wv [(size_t)DIMX * DI];      // 4 MB: gamma-folded Wv
__device__ float g_rs [MROWS];                  // per-row rmsnorm scale
__device__ float g_G  [(size_t)BQ * DI * DI];   // 16 MB: per-batch Gram of rs*x
__device__ float g_Tq [(size_t)BQ * DI * DI];   // 16 MB: G @ W'q
__device__ float g_Tk [(size_t)BQ * DI * DI];   // 16 MB: G @ W'k
__device__ float g_M  [(size_t)BQ * DI * DI];   // 16 MB: per-batch attn-contracted w_out
__device__ float g_M2 [(size_t)BQ * DI * DI];   // 16 MB: W'v @ M
__device__ float g_sim [64 * 64 * 64];
__device__ float g_attn[64 * 64 * 64];
__device__ float g_ssq[64 * 64];
__device__ float g_ssk[64 * 64];

// ---------------- f32x2 helpers ----------------
__device__ __forceinline__ u64 pk2(float lo, float hi) {
    u64 r;
    asm("mov.b64 %0, {%1, %2};" : "=l"(r)
        : "r"(__float_as_uint(lo)), "r"(__float_as_uint(hi)));
    return r;
}
__device__ __forceinline__ u64 pkdup(float v) {
    u64 r;
    asm("mov.b64 %0, {%1, %1};" : "=l"(r) : "r"(__float_as_uint(v)));
    return r;
}
__device__ __forceinline__ void unpk2(u64 u, float& lo, float& hi) {
    unsigned int a, b;
    asm("mov.b64 {%0, %1}, %2;" : "=r"(a), "=r"(b) : "l"(u));
    lo = __uint_as_float(a);
    hi = __uint_as_float(b);
}
#define FFMA2(c, a, b) asm("fma.rn.f32x2 %0, %1, %2, %0;" : "+l"(c) : "l"(a), "l"(b))

// ---------------- kernel 0a: fold gamma into w_qkv, split into 3 planes ----------------
__global__ __launch_bounds__(256) void k_wfold3(const float* __restrict__ w,
                                                const float* __restrict__ gamma) {
    int idx = blockIdx.x * 256 + threadIdx.x;   // float4 index over [1024 x 3072]
    int m = idx / (QKVN / 4);
    int cg = (idx % (QKVN / 4)) * 4;
    float g = gamma[m];
    float4 v = ((const float4*)w)[idx];
    v.x *= g; v.y *= g; v.z *= g; v.w *= g;
    int plane = cg >> 10, cc = cg & 1023;
    float* dst = (plane == 0) ? g_wqp : (plane == 1) ? g_wk : g_wv;
    *(float4*)&dst[(size_t)m * DI + cc] = v;
}

// ---------------- kernel 0b: per-row rmsnorm scales ----------------
__global__ __launch_bounds__(256) void k_rscale(const float* __restrict__ x) {
    int row = blockIdx.x;
    int t = threadIdx.x;
    float4 v = ((const float4*)(x + (size_t)row * DIMX))[t];
    float ss = v.x * v.x + v.y * v.y + v.z * v.z + v.w * v.w;
    __shared__ float red[8];
    #pragma unroll
    for (int o = 16; o; o >>= 1) ss += __shfl_xor_sync(0xffffffffu, ss, o);
    if ((t & 31) == 0) red[t >> 5] = ss;
    __syncthreads();
    if (t < 8) {
        float s2 = red[t];
        #pragma unroll
        for (int o = 4; o; o >>= 1) s2 += __shfl_xor_sync(0xffu, s2, o);
        if (t == 0) g_rs[row] = 32.0f / fmaxf(sqrtf(s2), 1e-12f);
    }
}

// ---------------- GEMM body (proven core): C[row0.., col0..] += A[1024-stride] @ B[1024-stride]
#define ASTRIDE 132
template <bool RSCALE>
__device__ __forceinline__ void gemm_body(const float* __restrict__ A,
                                          const float* __restrict__ Bm,
                                          float* __restrict__ C,
                                          const float* __restrict__ rs,
                                          int row0) {
    constexpr int K = 1024;
    __shared__ float As[2][16][ASTRIDE];
    __shared__ float Bs[2][16][128];

    const int tid = threadIdx.x;
    const int tx = tid & 15;
    const int ty = tid >> 4;
    const int col0 = blockIdx.x * 128;

    const int ar = tid >> 2;
    const int ak = (tid & 3) * 4;
    const int bk = tid >> 5;
    const int bn = (tid & 31) * 4;

    const float* Aptr = A + (size_t)(row0 + ar) * K + ak;
    const float* Bptr = Bm + (size_t)bk * DI + col0 + bn;

    u64 acc[8][4];
    #pragma unroll
    for (int i = 0; i < 8; i++)
        #pragma unroll
        for (int j = 0; j < 4; j++) acc[i][j] = 0ull;

    float4 a0 = *(const float4*)Aptr;
    float4 a1 = *(const float4*)(Aptr + (size_t)64 * K);
    float4 b0 = *(const float4*)Bptr;
    float4 b1 = *(const float4*)(Bptr + (size_t)8 * DI);

    As[0][ak + 0][ar] = a0.x; As[0][ak + 1][ar] = a0.y;
    As[0][ak + 2][ar] = a0.z; As[0][ak + 3][ar] = a0.w;
    As[0][ak + 0][64 + ar] = a1.x; As[0][ak + 1][64 + ar] = a1.y;
    As[0][ak + 2][64 + ar] = a1.z; As[0][ak + 3][64 + ar] = a1.w;
    *(float4*)&Bs[0][bk][bn] = b0;
    *(float4*)&Bs[0][bk + 8][bn] = b1;
    __syncthreads();

    const int NT = K / 16;
    for (int t = 0; t < NT; t++) {
        const int cur = t & 1;
        if (t + 1 < NT) {
            const float* Ap = A + (size_t)(row0 + ar) * K + (t + 1) * 16 + ak;
            a0 = *(const float4*)Ap;
            a1 = *(const float4*)(Ap + (size_t)64 * K);
            const float* Bp = Bm + (size_t)((t + 1) * 16 + bk) * DI + col0 + bn;
            b0 = *(const float4*)Bp;
            b1 = *(const float4*)(Bp + (size_t)8 * DI);
        }
        #pragma unroll
        for (int k = 0; k < 16; k++) {
            float4 av0 = *(const float4*)&As[cur][k][ty * 4];
            float4 av1 = *(const float4*)&As[cur][k][64 + ty * 4];
            float4 bv0 = *(const float4*)&Bs[cur][k][tx * 4];
            float4 bv1 = *(const float4*)&Bs[cur][k][64 + tx * 4];
            u64 bp0 = pk2(bv0.x, bv0.y), bp1 = pk2(bv0.z, bv0.w);
            u64 bp2 = pk2(bv1.x, bv1.y), bp3 = pk2(bv1.z, bv1.w);
            float a[8] = {av0.x, av0.y, av0.z, av0.w, av1.x, av1.y, av1.z, av1.w};
            #pragma unroll
            for (int i = 0; i < 8; i++) {
                u64 ap = pkdup(a[i]);
                FFMA2(acc[i][0], ap, bp0);
                FFMA2(acc[i][1], ap, bp1);
                FFMA2(acc[i][2], ap, bp2);
                FFMA2(acc[i][3], ap, bp3);
            }
        }
        if (t + 1 < NT) {
            const int nxt = cur ^ 1;
            As[nxt][ak + 0][ar] = a0.x; As[nxt][ak + 1][ar] = a0.y;
            As[nxt][ak + 2][ar] = a0.z; As[nxt][ak + 3][ar] = a0.w;
            As[nxt][ak + 0][64 + ar] = a1.x; As[nxt][ak + 1][64 + ar] = a1.y;
            As[nxt][ak + 2][64 + ar] = a1.z; As[nxt][ak + 3][64 + ar] = a1.w;
            *(float4*)&Bs[nxt][bk][bn] = b0;
            *(float4*)&Bs[nxt][bk + 8][bn] = b1;
            __syncthreads();
        }
    }

    #pragma unroll
    for (int i = 0; i < 8; i++) {
        int r = row0 + ((i < 4) ? (ty * 4 + i) : (64 + ty * 4 + i - 4));
        float x0, x1, x2, x3, x4, x5, x6, x7;
        unpk2(acc[i][0], x0, x1);
        unpk2(acc[i][1], x2, x3);
        unpk2(acc[i][2], x4, x5);
        unpk2(acc[i][3], x6, x7);
        if (RSCALE) {
            float s = rs[r];
            x0 *= s; x1 *= s; x2 *= s; x3 *= s;
            x4 *= s; x5 *= s; x6 *= s; x7 *= s;
        }
        float4 o0 = make_float4(x0, x1, x2, x3);
        float4 o1 = make_float4(x4, x5, x6, x7);
        *(float4*)&C[(size_t)r * DI + col0 + tx * 4] = o0;
        *(float4*)&C[(size_t)r * DI + col0 + 64 + tx * 4] = o1;
    }
}

// T_q / T_k = G_b @ W'  (grid (8, 64): y = op*32 + b*8 + ytile)
__global__ __launch_bounds__(256, 2) void k_T() {
    const int op = blockIdx.y >> 5;
    const int rem = blockIdx.y & 31;
    const int b = rem >> 3, yt = rem & 7;
    const float* A = g_G + (size_t)b * DI * DI;
    const float* B = op ? g_wk : g_wqp;
    float* C = (op ? g_Tk : g_Tq) + (size_t)b * DI * DI;
    gemm_body<false>(A, B, C, nullptr, yt * 128);
}
// M2_b = W'v @ M_b  (grid (8, 32))
__global__ __launch_bounds__(256, 2) void k_MM() {
    const int b = blockIdx.y >> 3, yt = blockIdx.y & 7;
    gemm_body<false>(g_wv, g_M + (size_t)b * DI * DI, g_M2 + (size_t)b * DI * DI,
                     nullptr, yt * 128);
}
// out = rs * (x @ M2_b)  (grid (8, 128))
__global__ __launch_bounds__(256, 2) void k_out(const float* __restrict__ x,
                                                float* __restrict__ out) {
    const int b = blockIdx.y >> 5;
    gemm_body<true>(x, g_M2 + (size_t)b * DI * DI, out, g_rs, blockIdx.y * 128);
}

// ---------------- SYRK: G_b = sum_n (rs*x)(rs*x)^T, K=4096, grid (8, 32) ----------------
__global__ __launch_bounds__(256, 2) void k_syrk(const float* __restrict__ x) {
    constexpr int K = SEQ;  // 4096
    __shared__ float As[2][16][128];
    __shared__ float Bs[2][16][128];

    const int tid = threadIdx.x;
    const int tx = tid & 15;
    const int ty = tid >> 4;
    const int b = blockIdx.y >> 3;
    const int m0 = (blockIdx.y & 7) * 128;
    const int n0 = blockIdx.x * 128;

    const float* xb = x + (size_t)b * SEQ * DIMX;
    const float* rsb = g_rs + b * SEQ;

    // staging map (B-style both sides): f = tid + i*256 -> kk = f>>5, c4 = (f&31)*4
    const int kk0 = tid >> 5, c40 = (tid & 31) * 4;      // i=0 (kk 0..7)
    const int kk1 = kk0 + 8;                              // i=1 (kk 8..15)

    u64 acc[8][4];
    #pragma unroll
    for (int i = 0; i < 8; i++)
        #pragma unroll
        for (int j = 0; j < 4; j++) acc[i][j] = 0ull;

    float4 am0, am1, bn0, bn1;
    float r0 = rsb[kk0], r1 = rsb[kk1];
    am0 = *(const float4*)(xb + (size_t)kk0 * DIMX + m0 + c40);
    am1 = *(const float4*)(xb + (size_t)kk1 * DIMX + m0 + c40);
    bn0 = *(const float4*)(xb + (size_t)kk0 * DIMX + n0 + c40);
    bn1 = *(const float4*)(xb + (size_t)kk1 * DIMX + n0 + c40);
    am0.x *= r0; am0.y *= r0; am0.z *= r0; am0.w *= r0;
    am1.x *= r1; am1.y *= r1; am1.z *= r1; am1.w *= r1;
    bn0.x *= r0; bn0.y *= r0; bn0.z *= r0; bn0.w *= r0;
    bn1.x *= r1; bn1.y *= r1; bn1.z *= r1; bn1.w *= r1;
    *(float4*)&As[0][kk0][c40] = am0;
    *(float4*)&As[0][kk1][c40] = am1;
    *(float4*)&Bs[0][kk0][c40] = bn0;
    *(float4*)&Bs[0][kk1][c40] = bn1;
    __syncthreads();

    const int NT = K / 16;
    for (int t = 0; t < NT; t++) {
        const int cur = t & 1;
        if (t + 1 < NT) {
            const int k0 = (t + 1) * 16;
            r0 = rsb[k0 + kk0];
            r1 = rsb[k0 + kk1];
            am0 = *(const float4*)(xb + (size_t)(k0 + kk0) * DIMX + m0 + c40);
            am1 = *(const float4*)(xb + (size_t)(k0 + kk1) * DIMX + m0 + c40);
            bn0 = *(const float4*)(xb + (size_t)(k0 + kk0) * DIMX + n0 + c40);
            bn1 = *(const float4*)(xb + (size_t)(k0 + kk1) * DIMX + n0 + c40);
            am0.x *= r0; am0.y *= r0; am0.z *= r0; am0.w *= r0;
            am1.x *= r1; am1.y *= r1; am1.z *= r1; am1.w *= r1;
            bn0.x *= r0; bn0.y *= r0; bn0.z *= r0; bn0.w *= r0;
            bn1.x *= r1; bn1.y *= r1; bn1.z *= r1; bn1.w *= r1;
        }
        #pragma unroll
        for (int k = 0; k < 16; k++) {
            float4 av0 = *(const float4*)&As[cur][k][ty * 4];
            float4 av1 = *(const float4*)&As[cur][k][64 + ty * 4];
            float4 bv0 = *(const float4*)&Bs[cur][k][tx * 4];
            float4 bv1 = *(const float4*)&Bs[cur][k][64 + tx * 4];
            u64 bp0 = pk2(bv0.x, bv0.y), bp1 = pk2(bv0.z, bv0.w);
            u64 bp2 = pk2(bv1.x, bv1.y), bp3 = pk2(bv1.z, bv1.w);
            float a[8] = {av0.x, av0.y, av0.z, av0.w, av1.x, av1.y, av1.z, av1.w};
            #pragma unroll
            for (int i = 0; i < 8; i++) {
                u64 ap = pkdup(a[i]);
                FFMA2(acc[i][0], ap, bp0);
                FFMA2(acc[i][1], ap, bp1);
                FFMA2(acc[i][2], ap, bp2);
                FFMA2(acc[i][3], ap, bp3);
            }
        }
        if (t + 1 < NT) {
            const int nxt = cur ^ 1;
            *(float4*)&As[nxt][kk0][c40] = am0;
            *(float4*)&As[nxt][kk1][c40] = am1;
            *(float4*)&Bs[nxt][kk0][c40] = bn0;
            *(float4*)&Bs[nxt][kk1][c40] = bn1;
            __syncthreads();
        }
    }

    float* Gb = g_G + (size_t)b * DI * DI;
    #pragma unroll
    for (int i = 0; i < 8; i++) {
        int r = m0 + ((i < 4) ? (ty * 4 + i) : (64 + ty * 4 + i - 4));
        float x0, x1, x2, x3, x4, x5, x6, x7;
        unpk2(acc[i][0], x0, x1);
        unpk2(acc[i][1], x2, x3);
        unpk2(acc[i][2], x4, x5);
        unpk2(acc[i][3], x6, x7);
        *(float4*)&Gb[(size_t)r * DI + n0 + tx * 4] = make_float4(x0, x1, x2, x3);
        *(float4*)&Gb[(size_t)r * DI + n0 + 64 + tx * 4] = make_float4(x4, x5, x6, x7);
    }
}

// ---------------- sim + diag: sim = W'q^T Tk (per bh), ssq = diag(W'q.Tq), ssk = diag(W'k.Tk)
__global__ __launch_bounds__(256) void k_simdiag() {
    const int bh = blockIdx.x;
    const int b = bh >> 4, h = bh & 15;
    const int tid = threadIdx.x;
    const int tx = tid & 15, ty = tid >> 4;

    __shared__ float qs[32][64];
    __shared__ float ks[32][64];
    __shared__ float red[2][64];
    if (tid < 64) { red[0][tid] = 0.0f; red[1][tid] = 0.0f; }

    float acc[4][4];
    #pragma unroll
    for (int i = 0; i < 4; i++)
        #pragma unroll
        for (int j = 0; j < 4; j++) acc[i][j] = 0.0f;
    float sq[4] = {0, 0, 0, 0}, sk[4] = {0, 0, 0, 0};

    const int nnA = tid >> 4, dA = (tid & 15) * 4;
    const float* wqp = g_wqp + h * 64;
    const float* wkp = g_wk + h * 64;
    const float* tqp = g_Tq + (size_t)b * DI * DI + h * 64;
    const float* tkp = g_Tk + (size_t)b * DI * DI + h * 64;

    for (int t = 0; t < 32; t++) {
        const int m = t * 32;
        float4 wq0 = *(const float4*)(wqp + (size_t)(m + nnA) * DI + dA);
        float4 wq1 = *(const float4*)(wqp + (size_t)(m + nnA + 16) * DI + dA);
        float4 tk0 = *(const float4*)(tkp + (size_t)(m + nnA) * DI + dA);
        float4 tk1 = *(const float4*)(tkp + (size_t)(m + nnA + 16) * DI + dA);
        float4 tq0 = *(const float4*)(tqp + (size_t)(m + nnA) * DI + dA);
        float4 tq1 = *(const float4*)(tqp + (size_t)(m + nnA + 16) * DI + dA);
        float4 wk0 = *(const float4*)(wkp + (size_t)(m + nnA) * DI + dA);
        float4 wk1 = *(const float4*)(wkp + (size_t)(m + nnA + 16) * DI + dA);

        sq[0] += wq0.x * tq0.x + wq1.x * tq1.x;
        sq[1] += wq0.y * tq0.y + wq1.y * tq1.y;
        sq[2] += wq0.z * tq0.z + wq1.z * tq1.z;
        sq[3] += wq0.w * tq0.w + wq1.w * tq1.w;
        sk[0] += wk0.x * tk0.x + wk1.x * tk1.x;
        sk[1] += wk0.y * tk0.y + wk1.y * tk1.y;
        sk[2] += wk0.z * tk0.z + wk1.z * tk1.z;
        sk[3] += wk0.w * tk0.w + wk1.w * tk1.w;

        __syncthreads();
        *(float4*)&qs[nnA][dA] = wq0;
        *(float4*)&qs[nnA + 16][dA] = wq1;
        *(float4*)&ks[nnA][dA] = tk0;
        *(float4*)&ks[nnA + 16][dA] = tk1;
        __syncthreads();

        #pragma unroll 8
        for (int nn = 0; nn < 32; nn++) {
            float4 qa = *(const float4*)&qs[nn][ty * 4];
            float4 kb = *(const float4*)&ks[nn][tx * 4];
            float aa[4] = {qa.x, qa.y, qa.z, qa.w};
            float bb[4] = {kb.x, kb.y, kb.z, kb.w};
            #pragma unroll
            for (int i = 0; i < 4; i++)
                #pragma unroll
                for (int j = 0; j < 4; j++)
                    acc[i][j] = fmaf(aa[i], bb[j], acc[i][j]);
        }
    }

    // sim: single-owner direct write
    float* simp = g_sim + bh * 4096;
    #pragma unroll
    for (int i = 0; i < 4; i++)
        #pragma unroll
        for (int j = 0; j < 4; j++)
            simp[(ty * 4 + i) * 64 + tx * 4 + j] = acc[i][j];

    // diag: smem reduce across the 16 nnA groups
    __syncthreads();
    #pragma unroll
    for (int c = 0; c < 4; c++) {
        atomicAdd(&red[0][dA + c], sq[c]);
        atomicAdd(&red[1][dA + c], sk[c]);
    }
    __syncthreads();
    if (tid < 64) {
        g_ssq[bh * 64 + tid] = red[0][tid];
        g_ssk[bh * 64 + tid] = red[1][tid];
    }
}

// ---------------- softmax (unchanged) ----------------
__global__ __launch_bounds__(256) void k_softmax(const float* __restrict__ temperature) {
    const int bh = blockIdx.x;
    const int tid = threadIdx.x;
    const int d = tid >> 2;
    const int sub = tid & 3;
    const int h = bh & 15;
    const float tscale = 8.0f * expf(temperature[h]);

    __shared__ float rk[64];
    if (tid < 64) rk[tid] = 1.0f / fmaxf(sqrtf(g_ssk[bh * 64 + tid]), 1e-12f);
    __syncthreads();

    const float rq = 1.0f / fmaxf(sqrtf(g_ssq[bh * 64 + d]), 1e-12f);
    const float* srow = g_sim + bh * 4096 + d * 64 + sub * 16;

    float s[16];
    float mx = -1e30f;
    const float sc = tscale * rq;
    #pragma unroll
    for (int j = 0; j < 16; j++) {
        s[j] = srow[j] * sc * rk[sub * 16 + j];
        mx = fmaxf(mx, s[j]);
    }
    mx = fmaxf(mx, __shfl_xor_sync(0xffffffffu, mx, 1));
    mx = fmaxf(mx, __shfl_xor_sync(0xffffffffu, mx, 2));
    float sum = 0.0f;
    #pragma unroll
    for (int j = 0; j < 16; j++) {
        s[j] = expf(s[j] - mx);
        sum += s[j];
    }
    sum += __shfl_xor_sync(0xffffffffu, sum, 1);
    sum += __shfl_xor_sync(0xffffffffu, sum, 2);
    const float inv = 1.0f / sum;
    float* arow = g_attn + bh * 4096 + d * 64 + sub * 16;
    #pragma unroll
    for (int j = 0; j < 16; j += 4) {
        float4 o = make_float4(s[j] * inv, s[j + 1] * inv, s[j + 2] * inv, s[j + 3] * inv);
        *(float4*)&arow[j] = o;
    }
}

// ---------------- k_M (unchanged): M_b[(h,e), j] = sum_d attn[b,h,d,e] * w_out[(h,d), j] ----
__global__ __launch_bounds__(256) void k_M(const float* __restrict__ W) {
    const int bh = blockIdx.x;
    const int j0 = blockIdx.y * 128;
    const int b = bh >> 4, h = bh & 15;
    const int tid = threadIdx.x;
    const int tx = tid & 15, ty = tid >> 4;

    __shared__ float am[64][64];
    __shared__ float ws[64][132];

    const float4* ap4 = (const float4*)(g_attn + bh * 4096);
    #pragma unroll
    for (int i = 0; i < 4; i++)
        ((float4*)am)[tid + i * 256] = ap4[tid + i * 256];
    #pragma unroll
    for (int i = 0; i < 8; i++) {
        int idx = tid + i * 256;
        int d = idx >> 5, jj = (idx & 31) * 4;
        *(float4*)&ws[d][jj] = *(const float4*)&W[(size_t)(h * 64 + d) * DI + j0 + jj];
    }
    __syncthreads();

    float acc[4][8];
    #pragma unroll
    for (int i = 0; i < 4; i++)
        #pragma unroll
        for (int j = 0; j < 8; j++) acc[i][j] = 0.0f;

    #pragma unroll 8
    for (int d = 0; d < 64; d++) {
        float4 a4 = *(const float4*)&am[d][ty * 4];
        float4 b0 = *(const float4*)&ws[d][tx * 8];
        float4 b1 = *(const float4*)&ws[d][tx * 8 + 4];
        float aa[4] = {a4.x, a4.y, a4.z, a4.w};
        float bb[8] = {b0.x, b0.y, b0.z, b0.w, b1.x, b1.y, b1.z, b1.w};
        #pragma unroll
        for (int i = 0; i < 4; i++)
            #pragma unroll
            for (int j = 0; j < 8; j++)
                acc[i][j] = fmaf(aa[i], bb[j], acc[i][j]);
    }

    #pragma unroll
    for (int i = 0; i < 4; i++) {
        int he = h * 64 + ty * 4 + i;
        float* mrow = g_M + ((size_t)b * DI + he) * DI + j0 + tx * 8;
        *(float4*)mrow       = make_float4(acc[i][0], acc[i][1], acc[i][2], acc[i][3]);
        *(float4*)(mrow + 4) = make_float4(acc[i][4], acc[i][5], acc[i][6], acc[i][7]);
    }
}

// ---------------- launch ----------------
extern "C" void kernel_launch(void* const* d_in, const int* in_sizes, int n_in,
                              void* d_out, int out_size) {
    const float* x = (const float*)d_in[0];
    const float* gamma = (const float*)d_in[1];
    const float* w_qkv = (const float*)d_in[2];
    const float* temperature = (const float*)d_in[3];
    const float* w_out = (const float*)d_in[4];
    float* out = (float*)d_out;

    k_wfold3<<<(DIMX * QKVN / 4) / 256, 256>>>(w_qkv, gamma);
    k_rscale<<<MROWS, 256>>>(x);
    k_syrk<<<dim3(8, 32), 256>>>(x);
    k_T<<<dim3(8, 64), 256>>>();
    k_simdiag<<<64, 256>>>();
    k_softmax<<<64, 256>>>(temperature);
    k_M<<<dim3(64, 8), 256>>>(w_out);
    k_MM<<<dim3(8, 32), 256>>>();
    k_out<<<dim3(8, 128), 256>>>(x, out);
}

// round 17
// speedup vs baseline: 1.6895x; 1.1724x over previous
#include <cuda_runtime.h>
#include <math.h>

// ---------------- problem constants ----------------
#define BQ     4
#define SEQ    4096
#define DIMX   1024
#define HEADS  16
#define DH     64
#define DI     1024
#define MROWS  (BQ*SEQ)     // 16384
#define QKVN   3072

typedef unsigned long long u64;

// ---------------- scratch (device globals; no allocation) ----------------
__device__ float g_wqp[(size_t)DIMX * DI];      // 4 MB: gamma-folded Wq
__device__ float g_wk [(size_t)DIMX * DI];      // 4 MB: gamma-folded Wk
__device__ float g_wv [(size_t)DIMX * DI];      // 4 MB: gamma-folded Wv
__device__ float g_rs [MROWS];                  // per-row rmsnorm scale
__device__ float g_G  [(size_t)BQ * DI * DI];   // 16 MB: per-batch Gram of rs*x (symmetric)
__device__ float g_Tq [(size_t)BQ * DI * DI];   // 16 MB: G @ W'q
__device__ float g_Tk [(size_t)BQ * DI * DI];   // 16 MB: G @ W'k
__device__ float g_M  [(size_t)BQ * DI * DI];   // 16 MB: per-batch attn-contracted w_out
__device__ float g_M2 [(size_t)BQ * DI * DI];   // 16 MB: W'v @ M
__device__ float g_sim [64 * 64 * 64];
__device__ float g_attn[64 * 64 * 64];
__device__ float g_ssq[64 * 64];
__device__ float g_ssk[64 * 64];

// ---------------- f32x2 helpers ----------------
__device__ __forceinline__ u64 pk2(float lo, float hi) {
    u64 r;
    asm("mov.b64 %0, {%1, %2};" : "=l"(r)
        : "r"(__float_as_uint(lo)), "r"(__float_as_uint(hi)));
    return r;
}
__device__ __forceinline__ u64 pkdup(float v) {
    u64 r;
    asm("mov.b64 %0, {%1, %1};" : "=l"(r) : "r"(__float_as_uint(v)));
    return r;
}
__device__ __forceinline__ void unpk2(u64 u, float& lo, float& hi) {
    unsigned int a, b;
    asm("mov.b64 {%0, %1}, %2;" : "=r"(a), "=r"(b) : "l"(u));
    lo = __uint_as_float(a);
    hi = __uint_as_float(b);
}
#define FFMA2(c, a, b) asm("fma.rn.f32x2 %0, %1, %2, %0;" : "+l"(c) : "l"(a), "l"(b))

// ---------------- kernel 0a: fold gamma into w_qkv, split into 3 planes ----------------
__global__ __launch_bounds__(256) void k_wfold3(const float* __restrict__ w,
                                                const float* __restrict__ gamma) {
    int idx = blockIdx.x * 256 + threadIdx.x;   // float4 index over [1024 x 3072]
    int m = idx / (QKVN / 4);
    int cg = (idx % (QKVN / 4)) * 4;
    float g = gamma[m];
    float4 v = ((const float4*)w)[idx];
    v.x *= g; v.y *= g; v.z *= g; v.w *= g;
    int plane = cg >> 10, cc = cg & 1023;
    float* dst = (plane == 0) ? g_wqp : (plane == 1) ? g_wk : g_wv;
    *(float4*)&dst[(size_t)m * DI + cc] = v;
}

// ---------------- kernel 0b: per-row rmsnorm scales ----------------
__global__ __launch_bounds__(256) void k_rscale(const float* __restrict__ x) {
    int row = blockIdx.x;
    int t = threadIdx.x;
    float4 v = ((const float4*)(x + (size_t)row * DIMX))[t];
    float ss = v.x * v.x + v.y * v.y + v.z * v.z + v.w * v.w;
    __shared__ float red[8];
    #pragma unroll
    for (int o = 16; o; o >>= 1) ss += __shfl_xor_sync(0xffffffffu, ss, o);
    if ((t & 31) == 0) red[t >> 5] = ss;
    __syncthreads();
    if (t < 8) {
        float s2 = red[t];
        #pragma unroll
        for (int o = 4; o; o >>= 1) s2 += __shfl_xor_sync(0xffu, s2, o);
        if (t == 0) g_rs[row] = 32.0f / fmaxf(sqrtf(s2), 1e-12f);
    }
}

// ---------------- GEMM body (proven core): C[row0.., col0..] = A[1024-stride] @ B[1024-stride]
#define ASTRIDE 132
template <bool RSCALE>
__device__ __forceinline__ void gemm_body(const float* __restrict__ A,
                                          const float* __restrict__ Bm,
                                          float* __restrict__ C,
                                          const float* __restrict__ rs,
                                          int row0) {
    constexpr int K = 1024;
    __shared__ float As[2][16][ASTRIDE];
    __shared__ float Bs[2][16][128];

    const int tid = threadIdx.x;
    const int tx = tid & 15;
    const int ty = tid >> 4;
    const int col0 = blockIdx.x * 128;

    const int ar = tid >> 2;
    const int ak = (tid & 3) * 4;
    const int bk = tid >> 5;
    const int bn = (tid & 31) * 4;

    const float* Aptr = A + (size_t)(row0 + ar) * K + ak;
    const float* Bptr = Bm + (size_t)bk * DI + col0 + bn;

    u64 acc[8][4];
    #pragma unroll
    for (int i = 0; i < 8; i++)
        #pragma unroll
        for (int j = 0; j < 4; j++) acc[i][j] = 0ull;

    float4 a0 = *(const float4*)Aptr;
    float4 a1 = *(const float4*)(Aptr + (size_t)64 * K);
    float4 b0 = *(const float4*)Bptr;
    float4 b1 = *(const float4*)(Bptr + (size_t)8 * DI);

    As[0][ak + 0][ar] = a0.x; As[0][ak + 1][ar] = a0.y;
    As[0][ak + 2][ar] = a0.z; As[0][ak + 3][ar] = a0.w;
    As[0][ak + 0][64 + ar] = a1.x; As[0][ak + 1][64 + ar] = a1.y;
    As[0][ak + 2][64 + ar] = a1.z; As[0][ak + 3][64 + ar] = a1.w;
    *(float4*)&Bs[0][bk][bn] = b0;
    *(float4*)&Bs[0][bk + 8][bn] = b1;
    __syncthreads();

    const int NT = K / 16;
    for (int t = 0; t < NT; t++) {
        const int cur = t & 1;
        if (t + 1 < NT) {
            const float* Ap = A + (size_t)(row0 + ar) * K + (t + 1) * 16 + ak;
            a0 = *(const float4*)Ap;
            a1 = *(const float4*)(Ap + (size_t)64 * K);
            const float* Bp = Bm + (size_t)((t + 1) * 16 + bk) * DI + col0 + bn;
            b0 = *(const float4*)Bp;
            b1 = *(const float4*)(Bp + (size_t)8 * DI);
        }
        #pragma unroll
        for (int k = 0; k < 16; k++) {
            float4 av0 = *(const float4*)&As[cur][k][ty * 4];
            float4 av1 = *(const float4*)&As[cur][k][64 + ty * 4];
            float4 bv0 = *(const float4*)&Bs[cur][k][tx * 4];
            float4 bv1 = *(const float4*)&Bs[cur][k][64 + tx * 4];
            u64 bp0 = pk2(bv0.x, bv0.y), bp1 = pk2(bv0.z, bv0.w);
            u64 bp2 = pk2(bv1.x, bv1.y), bp3 = pk2(bv1.z, bv1.w);
            float a[8] = {av0.x, av0.y, av0.z, av0.w, av1.x, av1.y, av1.z, av1.w};
            #pragma unroll
            for (int i = 0; i < 8; i++) {
                u64 ap = pkdup(a[i]);
                FFMA2(acc[i][0], ap, bp0);
                FFMA2(acc[i][1], ap, bp1);
                FFMA2(acc[i][2], ap, bp2);
                FFMA2(acc[i][3], ap, bp3);
            }
        }
        if (t + 1 < NT) {
            const int nxt = cur ^ 1;
            As[nxt][ak + 0][ar] = a0.x; As[nxt][ak + 1][ar] = a0.y;
            As[nxt][ak + 2][ar] = a0.z; As[nxt][ak + 3][ar] = a0.w;
            As[nxt][ak + 0][64 + ar] = a1.x; As[nxt][ak + 1][64 + ar] = a1.y;
            As[nxt][ak + 2][64 + ar] = a1.z; As[nxt][ak + 3][64 + ar] = a1.w;
            *(float4*)&Bs[nxt][bk][bn] = b0;
            *(float4*)&Bs[nxt][bk + 8][bn] = b1;
            __syncthreads();
        }
    }

    #pragma unroll
    for (int i = 0; i < 8; i++) {
        int r = row0 + ((i < 4) ? (ty * 4 + i) : (64 + ty * 4 + i - 4));
        float x0, x1, x2, x3, x4, x5, x6, x7;
        unpk2(acc[i][0], x0, x1);
        unpk2(acc[i][1], x2, x3);
        unpk2(acc[i][2], x4, x5);
        unpk2(acc[i][3], x6, x7);
        if (RSCALE) {
            float s = rs[r];
            x0 *= s; x1 *= s; x2 *= s; x3 *= s;
            x4 *= s; x5 *= s; x6 *= s; x7 *= s;
        }
        float4 o0 = make_float4(x0, x1, x2, x3);
        float4 o1 = make_float4(x4, x5, x6, x7);
        *(float4*)&C[(size_t)r * DI + col0 + tx * 4] = o0;
        *(float4*)&C[(size_t)r * DI + col0 + 64 + tx * 4] = o1;
    }
}

// T_q / T_k = G_b @ W'  (grid (8, 64): y = op*32 + b*8 + ytile)
__global__ __launch_bounds__(256, 2) void k_T() {
    const int op = blockIdx.y >> 5;
    const int rem = blockIdx.y & 31;
    const int b = rem >> 3, yt = rem & 7;
    const float* A = g_G + (size_t)b * DI * DI;
    const float* B = op ? g_wk : g_wqp;
    float* C = (op ? g_Tk : g_Tq) + (size_t)b * DI * DI;
    gemm_body<false>(A, B, C, nullptr, yt * 128);
}
// M2_b = W'v @ M_b  (grid (8, 32))
__global__ __launch_bounds__(256, 2) void k_MM() {
    const int b = blockIdx.y >> 3, yt = blockIdx.y & 7;
    gemm_body<false>(g_wv, g_M + (size_t)b * DI * DI, g_M2 + (size_t)b * DI * DI,
                     nullptr, yt * 128);
}
// out = rs * (x @ M2_b)  (grid (8, 128))
__global__ __launch_bounds__(256, 2) void k_out(const float* __restrict__ x,
                                                float* __restrict__ out) {
    const int b = blockIdx.y >> 5;
    gemm_body<true>(x, g_M2 + (size_t)b * DI * DI, out, g_rs, blockIdx.y * 128);
}

// ---------------- SYRK (upper triangle only): G_b = sum_n (rs*x)(rs*x)^T, K=4096 ----------
// grid (36, 4): x = triangular 128-tile index (m_tile <= n_tile), y = batch. 144 blocks = 1 wave.
__global__ __launch_bounds__(256, 2) void k_syrk(const float* __restrict__ x) {
    constexpr int K = SEQ;  // 4096
    __shared__ float As[2][16][128];
    __shared__ float Bs[2][16][128];

    const int tid = threadIdx.x;
    const int tx = tid & 15;
    const int ty = tid >> 4;
    const int b = blockIdx.y;

    // unpack triangular tile index -> (mt, nt) with mt <= nt
    int ti = blockIdx.x;
    int mt = 0;
    while (ti >= 8 - mt) { ti -= 8 - mt; mt++; }
    const int nt = mt + ti;
    const int m0 = mt * 128;
    const int n0 = nt * 128;

    const float* xb = x + (size_t)b * SEQ * DIMX;
    const float* rsb = g_rs + b * SEQ;

    const int kk0 = tid >> 5, c40 = (tid & 31) * 4;      // kk 0..7
    const int kk1 = kk0 + 8;                              // kk 8..15

    u64 acc[8][4];
    #pragma unroll
    for (int i = 0; i < 8; i++)
        #pragma unroll
        for (int j = 0; j < 4; j++) acc[i][j] = 0ull;

    float4 am0, am1, bn0, bn1;
    float r0 = rsb[kk0], r1 = rsb[kk1];
    am0 = *(const float4*)(xb + (size_t)kk0 * DIMX + m0 + c40);
    am1 = *(const float4*)(xb + (size_t)kk1 * DIMX + m0 + c40);
    bn0 = *(const float4*)(xb + (size_t)kk0 * DIMX + n0 + c40);
    bn1 = *(const float4*)(xb + (size_t)kk1 * DIMX + n0 + c40);
    am0.x *= r0; am0.y *= r0; am0.z *= r0; am0.w *= r0;
    am1.x *= r1; am1.y *= r1; am1.z *= r1; am1.w *= r1;
    bn0.x *= r0; bn0.y *= r0; bn0.z *= r0; bn0.w *= r0;
    bn1.x *= r1; bn1.y *= r1; bn1.z *= r1; bn1.w *= r1;
    *(float4*)&As[0][kk0][c40] = am0;
    *(float4*)&As[0][kk1][c40] = am1;
    *(float4*)&Bs[0][kk0][c40] = bn0;
    *(float4*)&Bs[0][kk1][c40] = bn1;
    __syncthreads();

    const int NT = K / 16;
    for (int t = 0; t < NT; t++) {
        const int cur = t & 1;
        if (t + 1 < NT) {
            const int k0 = (t + 1) * 16;
            r0 = rsb[k0 + kk0];
            r1 = rsb[k0 + kk1];
            am0 = *(const float4*)(xb + (size_t)(k0 + kk0) * DIMX + m0 + c40);
            am1 = *(const float4*)(xb + (size_t)(k0 + kk1) * DIMX + m0 + c40);
            bn0 = *(const float4*)(xb + (size_t)(k0 + kk0) * DIMX + n0 + c40);
            bn1 = *(const float4*)(xb + (size_t)(k0 + kk1) * DIMX + n0 + c40);
            am0.x *= r0; am0.y *= r0; am0.z *= r0; am0.w *= r0;
            am1.x *= r1; am1.y *= r1; am1.z *= r1; am1.w *= r1;
            bn0.x *= r0; bn0.y *= r0; bn0.z *= r0; bn0.w *= r0;
            bn1.x *= r1; bn1.y *= r1; bn1.z *= r1; bn1.w *= r1;
        }
        #pragma unroll
        for (int k = 0; k < 16; k++) {
            float4 av0 = *(const float4*)&As[cur][k][ty * 4];
            float4 av1 = *(const float4*)&As[cur][k][64 + ty * 4];
            float4 bv0 = *(const float4*)&Bs[cur][k][tx * 4];
            float4 bv1 = *(const float4*)&Bs[cur][k][64 + tx * 4];
            u64 bp0 = pk2(bv0.x, bv0.y), bp1 = pk2(bv0.z, bv0.w);
            u64 bp2 = pk2(bv1.x, bv1.y), bp3 = pk2(bv1.z, bv1.w);
            float a[8] = {av0.x, av0.y, av0.z, av0.w, av1.x, av1.y, av1.z, av1.w};
            #pragma unroll
            for (int i = 0; i < 8; i++) {
                u64 ap = pkdup(a[i]);
                FFMA2(acc[i][0], ap, bp0);
                FFMA2(acc[i][1], ap, bp1);
                FFMA2(acc[i][2], ap, bp2);
                FFMA2(acc[i][3], ap, bp3);
            }
        }
        if (t + 1 < NT) {
            const int nxt = cur ^ 1;
            *(float4*)&As[nxt][kk0][c40] = am0;
            *(float4*)&As[nxt][kk1][c40] = am1;
            *(float4*)&Bs[nxt][kk0][c40] = bn0;
            *(float4*)&Bs[nxt][kk1][c40] = bn1;
            __syncthreads();
        }
    }

    float* Gb = g_G + (size_t)b * DI * DI;
    #pragma unroll
    for (int i = 0; i < 8; i++) {
        int r = m0 + ((i < 4) ? (ty * 4 + i) : (64 + ty * 4 + i - 4));
        float x0, x1, x2, x3, x4, x5, x6, x7;
        unpk2(acc[i][0], x0, x1);
        unpk2(acc[i][1], x2, x3);
        unpk2(acc[i][2], x4, x5);
        unpk2(acc[i][3], x6, x7);
        *(float4*)&Gb[(size_t)r * DI + n0 + tx * 4] = make_float4(x0, x1, x2, x3);
        *(float4*)&Gb[(size_t)r * DI + n0 + 64 + tx * 4] = make_float4(x4, x5, x6, x7);
    }
}

// ---------------- mirror lower triangle of G from upper (32x32 smem transpose) ----------
// grid (32, 32, 4); active where row128 > col128.
__global__ __launch_bounds__(256) void k_gfill() {
    const int r32 = blockIdx.y, c32 = blockIdx.x;
    if ((r32 >> 2) <= (c32 >> 2)) return;      // only strictly-lower 128-tiles
    const int b = blockIdx.z;
    float* Gb = g_G + (size_t)b * DI * DI;

    __shared__ float tile[32][33];
    const int tx = threadIdx.x & 31, ty = threadIdx.x >> 5;  // 32 x 8
    // read upper source: G[c32*32 + i][r32*32 + j]
    #pragma unroll
    for (int i = 0; i < 32; i += 8)
        tile[ty + i][tx] = Gb[(size_t)(c32 * 32 + ty + i) * DI + r32 * 32 + tx];
    __syncthreads();
    // write lower: G[r32*32 + i][c32*32 + j] = tile[j][i]
    #pragma unroll
    for (int i = 0; i < 32; i += 8)
        Gb[(size_t)(r32 * 32 + ty + i) * DI + c32 * 32 + tx] = tile[tx][ty + i];
}

// ---------------- sim + diag: sim = W'q^T Tk (per bh), ssq/ssk = diag terms ----------------
__global__ __launch_bounds__(256) void k_simdiag() {
    const int bh = blockIdx.x;
    const int b = bh >> 4, h = bh & 15;
    const int tid = threadIdx.x;
    const int tx = tid & 15, ty = tid >> 4;

    __shared__ float qs[32][64];
    __shared__ float ks[32][64];
    __shared__ float red[2][64];
    if (tid < 64) { red[0][tid] = 0.0f; red[1][tid] = 0.0f; }

    float acc[4][4];
    #pragma unroll
    for (int i = 0; i < 4; i++)
        #pragma unroll
        for (int j = 0; j < 4; j++) acc[i][j] = 0.0f;
    float sq[4] = {0, 0, 0, 0}, sk[4] = {0, 0, 0, 0};

    const int nnA = tid >> 4, dA = (tid & 15) * 4;
    const float* wqp = g_wqp + h * 64;
    const float* wkp = g_wk + h * 64;
    const float* tqp = g_Tq + (size_t)b * DI * DI + h * 64;
    const float* tkp = g_Tk + (size_t)b * DI * DI + h * 64;

    for (int t = 0; t < 32; t++) {
        const int m = t * 32;
        float4 wq0 = *(const float4*)(wqp + (size_t)(m + nnA) * DI + dA);
        float4 wq1 = *(const float4*)(wqp + (size_t)(m + nnA + 16) * DI + dA);
        float4 tk0 = *(const float4*)(tkp + (size_t)(m + nnA) * DI + dA);
        float4 tk1 = *(const float4*)(tkp + (size_t)(m + nnA + 16) * DI + dA);
        float4 tq0 = *(const float4*)(tqp + (size_t)(m + nnA) * DI + dA);
        float4 tq1 = *(const float4*)(tqp + (size_t)(m + nnA + 16) * DI + dA);
        float4 wk0 = *(const float4*)(wkp + (size_t)(m + nnA) * DI + dA);
        float4 wk1 = *(const float4*)(wkp + (size_t)(m + nnA + 16) * DI + dA);

        sq[0] += wq0.x * tq0.x + wq1.x * tq1.x;
        sq[1] += wq0.y * tq0.y + wq1.y * tq1.y;
        sq[2] += wq0.z * tq0.z + wq1.z * tq1.z;
        sq[3] += wq0.w * tq0.w + wq1.w * tq1.w;
        sk[0] += wk0.x * tk0.x + wk1.x * tk1.x;
        sk[1] += wk0.y * tk0.y + wk1.y * tk1.y;
        sk[2] += wk0.z * tk0.z + wk1.z * tk1.z;
        sk[3] += wk0.w * tk0.w + wk1.w * tk1.w;

        __syncthreads();
        *(float4*)&qs[nnA][dA] = wq0;
        *(float4*)&qs[nnA + 16][dA] = wq1;
        *(float4*)&ks[nnA][dA] = tk0;
        *(float4*)&ks[nnA + 16][dA] = tk1;
        __syncthreads();

        #pragma unroll 8
        for (int nn = 0; nn < 32; nn++) {
            float4 qa = *(const float4*)&qs[nn][ty * 4];
            float4 kb = *(const float4*)&ks[nn][tx * 4];
            float aa[4] = {qa.x, qa.y, qa.z, qa.w};
            float bb[4] = {kb.x, kb.y, kb.z, kb.w};
            #pragma unroll
            for (int i = 0; i < 4; i++)
                #pragma unroll
                for (int j = 0; j < 4; j++)
                    acc[i][j] = fmaf(aa[i], bb[j], acc[i][j]);
        }
    }

    float* simp = g_sim + bh * 4096;
    #pragma unroll
    for (int i = 0; i < 4; i++)
        #pragma unroll
        for (int j = 0; j < 4; j++)
            simp[(ty * 4 + i) * 64 + tx * 4 + j] = acc[i][j];

    __syncthreads();
    #pragma unroll
    for (int c = 0; c < 4; c++) {
        atomicAdd(&red[0][dA + c], sq[c]);
        atomicAdd(&red[1][dA + c], sk[c]);
    }
    __syncthreads();
    if (tid < 64) {
        g_ssq[bh * 64 + tid] = red[0][tid];
        g_ssk[bh * 64 + tid] = red[1][tid];
    }
}

// ---------------- softmax (unchanged) ----------------
__global__ __launch_bounds__(256) void k_softmax(const float* __restrict__ temperature) {
    const int bh = blockIdx.x;
    const int tid = threadIdx.x;
    const int d = tid >> 2;
    const int sub = tid & 3;
    const int h = bh & 15;
    const float tscale = 8.0f * expf(temperature[h]);

    __shared__ float rk[64];
    if (tid < 64) rk[tid] = 1.0f / fmaxf(sqrtf(g_ssk[bh * 64 + tid]), 1e-12f);
    __syncthreads();

    const float rq = 1.0f / fmaxf(sqrtf(g_ssq[bh * 64 + d]), 1e-12f);
    const float* srow = g_sim + bh * 4096 + d * 64 + sub * 16;

    float s[16];
    float mx = -1e30f;
    const float sc = tscale * rq;
    #pragma unroll
    for (int j = 0; j < 16; j++) {
        s[j] = srow[j] * sc * rk[sub * 16 + j];
        mx = fmaxf(mx, s[j]);
    }
    mx = fmaxf(mx, __shfl_xor_sync(0xffffffffu, mx, 1));
    mx = fmaxf(mx, __shfl_xor_sync(0xffffffffu, mx, 2));
    float sum = 0.0f;
    #pragma unroll
    for (int j = 0; j < 16; j++) {
        s[j] = expf(s[j] - mx);
        sum += s[j];
    }
    sum += __shfl_xor_sync(0xffffffffu, sum, 1);
    sum += __shfl_xor_sync(0xffffffffu, sum, 2);
    const float inv = 1.0f / sum;
    float* arow = g_attn + bh * 4096 + d * 64 + sub * 16;
    #pragma unroll
    for (int j = 0; j < 16; j += 4) {
        float4 o = make_float4(s[j] * inv, s[j + 1] * inv, s[j + 2] * inv, s[j + 3] * inv);
        *(float4*)&arow[j] = o;
    }
}

// ---------------- k_M (unchanged): M_b[(h,e), j] = sum_d attn[b,h,d,e] * w_out[(h,d), j] ----
__global__ __launch_bounds__(256) void k_M(const float* __restrict__ W) {
    const int bh = blockIdx.x;
    const int j0 = blockIdx.y * 128;
    const int b = bh >> 4, h = bh & 15;
    const int tid = threadIdx.x;
    const int tx = tid & 15, ty = tid >> 4;

    __shared__ float am[64][64];
    __shared__ float ws[64][132];

    const float4* ap4 = (const float4*)(g_attn + bh * 4096);
    #pragma unroll
    for (int i = 0; i < 4; i++)
        ((float4*)am)[tid + i * 256] = ap4[tid + i * 256];
    #pragma unroll
    for (int i = 0; i < 8; i++) {
        int idx = tid + i * 256;
        int d = idx >> 5, jj = (idx & 31) * 4;
        *(float4*)&ws[d][jj] = *(const float4*)&W[(size_t)(h * 64 + d) * DI + j0 + jj];
    }
    __syncthreads();

    float acc[4][8];
    #pragma unroll
    for (int i = 0; i < 4; i++)
        #pragma unroll
        for (int j = 0; j < 8; j++) acc[i][j] = 0.0f;

    #pragma unroll 8
    for (int d = 0; d < 64; d++) {
        float4 a4 = *(const float4*)&am[d][ty * 4];
        float4 b0 = *(const float4*)&ws[d][tx * 8];
        float4 b1 = *(const float4*)&ws[d][tx * 8 + 4];
        float aa[4] = {a4.x, a4.y, a4.z, a4.w};
        float bb[8] = {b0.x, b0.y, b0.z, b0.w, b1.x, b1.y, b1.z, b1.w};
        #pragma unroll
        for (int i = 0; i < 4; i++)
            #pragma unroll
            for (int j = 0; j < 8; j++)
                acc[i][j] = fmaf(aa[i], bb[j], acc[i][j]);
    }

    #pragma unroll
    for (int i = 0; i < 4; i++) {
        int he = h * 64 + ty * 4 + i;
        float* mrow = g_M + ((size_t)b * DI + he) * DI + j0 + tx * 8;
        *(float4*)mrow       = make_float4(acc[i][0], acc[i][1], acc[i][2], acc[i][3]);
        *(float4*)(mrow + 4) = make_float4(acc[i][4], acc[i][5], acc[i][6], acc[i][7]);
    }
}

// ---------------- launch ----------------
extern "C" void kernel_launch(void* const* d_in, const int* in_sizes, int n_in,
                              void* d_out, int out_size) {
    const float* x = (const float*)d_in[0];
    const float* gamma = (const float*)d_in[1];
    const float* w_qkv = (const float*)d_in[2];
    const float* temperature = (const float*)d_in[3];
    const float* w_out = (const float*)d_in[4];
    float* out = (float*)d_out;

    k_wfold3<<<(DIMX * QKVN / 4) / 256, 256>>>(w_qkv, gamma);
    k_rscale<<<MROWS, 256>>>(x);
    k_syrk<<<dim3(36, 4), 256>>>(x);
    k_gfill<<<dim3(32, 32, 4), 256>>>();
    k_T<<<dim3(8, 64), 256>>>();
    k_simdiag<<<64, 256>>>();
    k_softmax<<<64, 256>>>(temperature);
    k_M<<<dim3(64, 8), 256>>>(w_out);
    k_MM<<<dim3(8, 32), 256>>>();
    k_out<<<dim3(8, 128), 256>>>(x, out);
}